// round 4
// baseline (speedup 1.0000x reference)
#include <cuda_runtime.h>
#include <math.h>

#define Bsz  256
#define Tlen 512
#define IN   512
#define HID  1024
#define OUTD 512
#define G3   (3 * HID)

// Scratch: precomputed input projections [T][B][3H] (~1.6 GB) and ping-pong h.
__device__ float g_xpre[(size_t)Tlen * Bsz * G3];
__device__ float g_h[2][Bsz * HID];

// ---------------------------------------------------------------------------
__global__ void zero_h_kernel() {
    int i = blockIdx.x * blockDim.x + threadIdx.x;
    if (i < Bsz * HID) g_h[0][i] = 0.0f;
}

// ---------------------------------------------------------------------------
// X projection: out[t][b][g*H+j] = sum_i x[b][t][i] * Wx_g[j][i] + bx_g[j]
// M = B*T (m = b*T + t, matches x layout), N = 3072, K = 512.
// Tile 128x128x8, 256 threads, 8x8 microtile.
__global__ void gemm_x_kernel(const float* __restrict__ x,
                              const float* __restrict__ Wxr, const float* __restrict__ bxr,
                              const float* __restrict__ Wxc, const float* __restrict__ bxc,
                              const float* __restrict__ Wxz, const float* __restrict__ bxz) {
    const int BM = 128, BN = 128, BK = 8;
    __shared__ float As[BK][BM];
    __shared__ float Bs[BK][BN];

    const int n0 = blockIdx.x * BN;
    const int m0 = blockIdx.y * BM;
    const int g  = n0 >> 10;                    // 1024 % 128 == 0: whole block one gate
    const float* __restrict__ W    = (g == 0) ? Wxr : ((g == 1) ? Wxc : Wxz);
    const float* __restrict__ bias = (g == 0) ? bxr : ((g == 1) ? bxc : bxz);
    const int j0 = n0 - (g << 10);

    const int tid = threadIdx.x;
    const int a_row = tid >> 1;
    const int a_col = (tid & 1) * 4;

    const int tx = tid & 15;    // n micro index
    const int ty = tid >> 4;    // m micro index

    float acc[8][8];
#pragma unroll
    for (int i = 0; i < 8; i++)
#pragma unroll
        for (int j = 0; j < 8; j++) acc[i][j] = 0.0f;

    for (int k0 = 0; k0 < IN; k0 += BK) {
        float4 av = *(const float4*)(x + (size_t)(m0 + a_row) * IN + k0 + a_col);
        As[a_col + 0][a_row] = av.x;
        As[a_col + 1][a_row] = av.y;
        As[a_col + 2][a_row] = av.z;
        As[a_col + 3][a_row] = av.w;
        float4 bv = *(const float4*)(W + (size_t)(j0 + a_row) * IN + k0 + a_col);
        Bs[a_col + 0][a_row] = bv.x;
        Bs[a_col + 1][a_row] = bv.y;
        Bs[a_col + 2][a_row] = bv.z;
        Bs[a_col + 3][a_row] = bv.w;
        __syncthreads();

#pragma unroll
        for (int k = 0; k < BK; k++) {
            float4 a0 = *(const float4*)&As[k][ty * 8];
            float4 a1 = *(const float4*)&As[k][ty * 8 + 4];
            float4 b0 = *(const float4*)&Bs[k][tx * 8];
            float4 b1 = *(const float4*)&Bs[k][tx * 8 + 4];
            float a[8] = {a0.x, a0.y, a0.z, a0.w, a1.x, a1.y, a1.z, a1.w};
            float b[8] = {b0.x, b0.y, b0.z, b0.w, b1.x, b1.y, b1.z, b1.w};
#pragma unroll
            for (int i = 0; i < 8; i++)
#pragma unroll
                for (int j = 0; j < 8; j++)
                    acc[i][j] = fmaf(a[i], b[j], acc[i][j]);
        }
        __syncthreads();
    }

#pragma unroll
    for (int i = 0; i < 8; i++) {
        const int m = m0 + ty * 8 + i;
        const int b = m >> 9;          // / Tlen
        const int t = m & (Tlen - 1);
        const size_t base = ((size_t)t * Bsz + b) * G3 + n0;
#pragma unroll
        for (int j = 0; j < 8; j++) {
            const int nl = tx * 8 + j;
            g_xpre[base + nl] = acc[i][j] + bias[j0 + nl];
        }
    }
}

// ---------------------------------------------------------------------------
// One GRU timestep, fully fused: three gate GEMMs (shared h tile) + GRU update.
// Tiles: BM=32 (batch), BN=64 (hidden cols), BK=32. 128 threads, 4x4 micro x3.
// Grid: (16, 8) = 128 CTAs.
__global__ void gru_step_kernel(const float* __restrict__ Whr, const float* __restrict__ bhr,
                                const float* __restrict__ Whc, const float* __restrict__ bhc,
                                const float* __restrict__ Whz, const float* __restrict__ bhz,
                                int t) {
    const int BM = 32, BN = 64, BK = 32;
    __shared__ float Hs[BK][BM];
    __shared__ float Ws[3][BK][BN];

    const int par = t & 1;
    const float* __restrict__ hprev = g_h[par];
    float* __restrict__ hnext = g_h[par ^ 1];

    const int n0 = blockIdx.x * BN;
    const int m0 = blockIdx.y * BM;
    const int tid = threadIdx.x;   // 128

    // H load mapping: 32 rows x 4 k-quads of 8
    const int hr = tid >> 2;
    const int hq = (tid & 3) * 8;
    // W load mapping: 64 rows x 2 k-halves of 16
    const int wr = tid >> 1;
    const int wq = (tid & 1) * 16;

    const int tm = tid >> 4;   // 0..7  -> 4 batch rows
    const int tn = tid & 15;   // 0..15 -> 4 cols

    float ar[4][4], ac[4][4], az[4][4];
#pragma unroll
    for (int i = 0; i < 4; i++)
#pragma unroll
        for (int j = 0; j < 4; j++) { ar[i][j] = 0.f; ac[i][j] = 0.f; az[i][j] = 0.f; }

    const float* __restrict__ Wg[3] = {Whr, Whc, Whz};

    for (int k0 = 0; k0 < HID; k0 += BK) {
        {
            const float* hp = hprev + (size_t)(m0 + hr) * HID + k0 + hq;
            float4 h0 = *(const float4*)hp;
            float4 h1 = *(const float4*)(hp + 4);
            Hs[hq + 0][hr] = h0.x; Hs[hq + 1][hr] = h0.y;
            Hs[hq + 2][hr] = h0.z; Hs[hq + 3][hr] = h0.w;
            Hs[hq + 4][hr] = h1.x; Hs[hq + 5][hr] = h1.y;
            Hs[hq + 6][hr] = h1.z; Hs[hq + 7][hr] = h1.w;
        }
#pragma unroll
        for (int g = 0; g < 3; g++) {
            const float* wp = Wg[g] + (size_t)(n0 + wr) * HID + k0 + wq;
#pragma unroll
            for (int u = 0; u < 4; u++) {
                float4 wv = *(const float4*)(wp + u * 4);
                Ws[g][wq + u * 4 + 0][wr] = wv.x;
                Ws[g][wq + u * 4 + 1][wr] = wv.y;
                Ws[g][wq + u * 4 + 2][wr] = wv.z;
                Ws[g][wq + u * 4 + 3][wr] = wv.w;
            }
        }
        __syncthreads();

#pragma unroll
        for (int k = 0; k < BK; k++) {
            float4 hv = *(const float4*)&Hs[k][tm * 4];
            float4 wrv = *(const float4*)&Ws[0][k][tn * 4];
            float4 wcv = *(const float4*)&Ws[1][k][tn * 4];
            float4 wzv = *(const float4*)&Ws[2][k][tn * 4];
            float h4[4] = {hv.x, hv.y, hv.z, hv.w};
            float r4[4] = {wrv.x, wrv.y, wrv.z, wrv.w};
            float c4[4] = {wcv.x, wcv.y, wcv.z, wcv.w};
            float z4[4] = {wzv.x, wzv.y, wzv.z, wzv.w};
#pragma unroll
            for (int i = 0; i < 4; i++)
#pragma unroll
                for (int j = 0; j < 4; j++) {
                    ar[i][j] = fmaf(h4[i], r4[j], ar[i][j]);
                    ac[i][j] = fmaf(h4[i], c4[j], ac[i][j]);
                    az[i][j] = fmaf(h4[i], z4[j], az[i][j]);
                }
        }
        __syncthreads();
    }

    // Fused GRU elementwise update
#pragma unroll
    for (int i = 0; i < 4; i++) {
        const int b = m0 + tm * 4 + i;
        const size_t xbase = ((size_t)t * Bsz + b) * G3;
#pragma unroll
        for (int j = 0; j < 4; j++) {
            const int col = n0 + tn * 4 + j;
            const float xr = g_xpre[xbase + col];
            const float xc = g_xpre[xbase + HID + col];
            const float xz = g_xpre[xbase + 2 * HID + col];
            const float hold = hprev[(size_t)b * HID + col];
            const float r = 1.0f / (1.0f + expf(-(xr + ar[i][j] + bhr[col])));
            const float c = tanhf(xc + r * (ac[i][j] + bhc[col]));
            const float z = 1.0f / (1.0f + expf(-(xz + az[i][j] + bhz[col])));
            hnext[(size_t)b * HID + col] = (1.0f - z) * hold + z * c;
        }
    }
}

// ---------------------------------------------------------------------------
// out[b][o] = sum_k h_final[b][k] * Wo[o][k] + bo[o]   (h_final = g_h[0])
// BM=32, BN=64, BK=32, 128 threads, 4x4 micro. Grid (8, 8).
__global__ void gemm_out_kernel(const float* __restrict__ Wo, const float* __restrict__ bo,
                                float* __restrict__ out) {
    const int BM = 32, BN = 64, BK = 32;
    __shared__ float Hs[BK][BM];
    __shared__ float Ws[BK][BN];

    const float* __restrict__ h = g_h[0];
    const int n0 = blockIdx.x * BN;
    const int m0 = blockIdx.y * BM;
    const int tid = threadIdx.x;

    const int hr = tid >> 2;
    const int hq = (tid & 3) * 8;
    const int wr = tid >> 1;
    const int wq = (tid & 1) * 16;
    const int tm = tid >> 4;
    const int tn = tid & 15;

    float acc[4][4];
#pragma unroll
    for (int i = 0; i < 4; i++)
#pragma unroll
        for (int j = 0; j < 4; j++) acc[i][j] = 0.f;

    for (int k0 = 0; k0 < HID; k0 += BK) {
        {
            const float* hp = h + (size_t)(m0 + hr) * HID + k0 + hq;
            float4 h0 = *(const float4*)hp;
            float4 h1 = *(const float4*)(hp + 4);
            Hs[hq + 0][hr] = h0.x; Hs[hq + 1][hr] = h0.y;
            Hs[hq + 2][hr] = h0.z; Hs[hq + 3][hr] = h0.w;
            Hs[hq + 4][hr] = h1.x; Hs[hq + 5][hr] = h1.y;
            Hs[hq + 6][hr] = h1.z; Hs[hq + 7][hr] = h1.w;
        }
        {
            const float* wp = Wo + (size_t)(n0 + wr) * HID + k0 + wq;
#pragma unroll
            for (int u = 0; u < 4; u++) {
                float4 wv = *(const float4*)(wp + u * 4);
                Ws[wq + u * 4 + 0][wr] = wv.x;
                Ws[wq + u * 4 + 1][wr] = wv.y;
                Ws[wq + u * 4 + 2][wr] = wv.z;
                Ws[wq + u * 4 + 3][wr] = wv.w;
            }
        }
        __syncthreads();

#pragma unroll
        for (int k = 0; k < BK; k++) {
            float4 hv = *(const float4*)&Hs[k][tm * 4];
            float4 wv = *(const float4*)&Ws[k][tn * 4];
            float h4[4] = {hv.x, hv.y, hv.z, hv.w};
            float w4[4] = {wv.x, wv.y, wv.z, wv.w};
#pragma unroll
            for (int i = 0; i < 4; i++)
#pragma unroll
                for (int j = 0; j < 4; j++)
                    acc[i][j] = fmaf(h4[i], w4[j], acc[i][j]);
        }
        __syncthreads();
    }

#pragma unroll
    for (int i = 0; i < 4; i++) {
        const int b = m0 + tm * 4 + i;
#pragma unroll
        for (int j = 0; j < 4; j++) {
            const int o = n0 + tn * 4 + j;
            out[(size_t)b * OUTD + o] = acc[i][j] + bo[o];
        }
    }
}

// ---------------------------------------------------------------------------
extern "C" void kernel_launch(void* const* d_in, const int* in_sizes, int n_in,
                              void* d_out, int out_size) {
    const float* x   = (const float*)d_in[0];
    const float* Wxr = (const float*)d_in[1];
    const float* bxr = (const float*)d_in[2];
    const float* Whr = (const float*)d_in[3];
    const float* bhr = (const float*)d_in[4];
    const float* Wxc = (const float*)d_in[5];
    const float* bxc = (const float*)d_in[6];
    const float* Whc = (const float*)d_in[7];
    const float* bhc = (const float*)d_in[8];
    const float* Wxz = (const float*)d_in[9];
    const float* bxz = (const float*)d_in[10];
    const float* Whz = (const float*)d_in[11];
    const float* bhz = (const float*)d_in[12];
    const float* Wo  = (const float*)d_in[13];
    const float* bo  = (const float*)d_in[14];
    float* out = (float*)d_out;

    zero_h_kernel<<<(Bsz * HID + 255) / 256, 256>>>();
    gemm_x_kernel<<<dim3(G3 / 128, (Bsz * Tlen) / 128), 256>>>(x, Wxr, bxr, Wxc, bxc, Wxz, bxz);
    for (int t = 0; t < Tlen; t++)
        gru_step_kernel<<<dim3(HID / 64, Bsz / 32), 128>>>(Whr, bhr, Whc, bhc, Whz, bhz, t);
    gemm_out_kernel<<<dim3(OUTD / 64, Bsz / 32), 128>>>(Wo, bo, out);
}

// round 6
// speedup vs baseline: 1.3087x; 1.3087x over previous
#include <cuda_runtime.h>
#include <math.h>

#define Bsz  256
#define Tlen 512
#define IN   512
#define HID  1024
#define OUTD 512
#define G3   (3 * HID)

#define NCTA      128
#define BN        8          // hidden columns per CTA (per gate)
#define BK        32         // k-chunk
#define HS_PITCH  258        // 256 + 2 pad
#define WS_ELEMS  (3 * HID * BN)            // 24576 floats
#define HS_ELEMS  (BK * HS_PITCH)           // 8256 floats per buffer
#define SMEM_BYTES ((WS_ELEMS + 2 * HS_ELEMS) * 4)

// Scratch: precomputed input projections [T][B][3H] (~1.6 GB), ping-pong h, barrier.
__device__ float g_xpre[(size_t)Tlen * Bsz * G3];
__device__ float g_h[2][Bsz * HID];
__device__ unsigned g_bar;

// ---------------------------------------------------------------------------
typedef unsigned long long u64;

__device__ __forceinline__ u64 pack2(float lo, float hi) {
    u64 r; asm("mov.b64 %0, {%1, %2};" : "=l"(r) : "f"(lo), "f"(hi)); return r;
}
__device__ __forceinline__ void unpack2(u64 v, float& lo, float& hi) {
    asm("mov.b64 {%0, %1}, %2;" : "=f"(lo), "=f"(hi) : "l"(v));
}
__device__ __forceinline__ u64 fma2(u64 a, u64 b, u64 c) {
    u64 d; asm("fma.rn.f32x2 %0, %1, %2, %3;" : "=l"(d) : "l"(a), "l"(b), "l"(c)); return d;
}
__device__ __forceinline__ float sigf(float x) {
    return 1.0f / (1.0f + __expf(-x));
}

// ---------------------------------------------------------------------------
__global__ void zero_h_kernel() {
    int i = blockIdx.x * blockDim.x + threadIdx.x;
    if (i < Bsz * HID) g_h[0][i] = 0.0f;
    if (i == 0) g_bar = 0u;
}

// ---------------------------------------------------------------------------
// X projection: out[t][b][g*H+j] = x[b][t] . Wx_g[j] + bx_g[j]
// M = B*T, N = 3072, K = 512. Tile 128x128x8, 256 threads, 8x8 micro, FFMA2.
__global__ void gemm_x_kernel(const float* __restrict__ x,
                              const float* __restrict__ Wxr, const float* __restrict__ bxr,
                              const float* __restrict__ Wxc, const float* __restrict__ bxc,
                              const float* __restrict__ Wxz, const float* __restrict__ bxz) {
    const int BM = 128, BNx = 128, BKx = 8;
    __shared__ float As[BKx][BM];
    __shared__ float Bs[BKx][BNx];

    const int n0 = blockIdx.x * BNx;
    const int m0 = blockIdx.y * BM;
    const int g  = n0 >> 10;
    const float* __restrict__ W    = (g == 0) ? Wxr : ((g == 1) ? Wxc : Wxz);
    const float* __restrict__ bias = (g == 0) ? bxr : ((g == 1) ? bxc : bxz);
    const int j0 = n0 - (g << 10);

    const int tid = threadIdx.x;
    const int a_row = tid >> 1;
    const int a_col = (tid & 1) * 4;
    const int tx = tid & 15;
    const int ty = tid >> 4;

    u64 acc[8][4];               // [row][col-pair] packed f32x2
#pragma unroll
    for (int i = 0; i < 8; i++)
#pragma unroll
        for (int j = 0; j < 4; j++) acc[i][j] = 0ull;

    for (int k0 = 0; k0 < IN; k0 += BKx) {
        float4 av = *(const float4*)(x + (size_t)(m0 + a_row) * IN + k0 + a_col);
        As[a_col + 0][a_row] = av.x;
        As[a_col + 1][a_row] = av.y;
        As[a_col + 2][a_row] = av.z;
        As[a_col + 3][a_row] = av.w;
        float4 bv = *(const float4*)(W + (size_t)(j0 + a_row) * IN + k0 + a_col);
        Bs[a_col + 0][a_row] = bv.x;
        Bs[a_col + 1][a_row] = bv.y;
        Bs[a_col + 2][a_row] = bv.z;
        Bs[a_col + 3][a_row] = bv.w;
        __syncthreads();

#pragma unroll
        for (int k = 0; k < BKx; k++) {
            float4 a0 = *(const float4*)&As[k][ty * 8];
            float4 a1 = *(const float4*)&As[k][ty * 8 + 4];
            const u64* bp = (const u64*)&Bs[k][tx * 8];
            u64 b0 = bp[0], b1 = bp[1], b2 = bp[2], b3 = bp[3];
            float a[8] = {a0.x, a0.y, a0.z, a0.w, a1.x, a1.y, a1.z, a1.w};
#pragma unroll
            for (int i = 0; i < 8; i++) {
                u64 ai = pack2(a[i], a[i]);
                acc[i][0] = fma2(ai, b0, acc[i][0]);
                acc[i][1] = fma2(ai, b1, acc[i][1]);
                acc[i][2] = fma2(ai, b2, acc[i][2]);
                acc[i][3] = fma2(ai, b3, acc[i][3]);
            }
        }
        __syncthreads();
    }

#pragma unroll
    for (int i = 0; i < 8; i++) {
        const int m = m0 + ty * 8 + i;
        const int b = m >> 9;
        const int t = m & (Tlen - 1);
        const size_t base = ((size_t)t * Bsz + b) * G3 + n0 + tx * 8;
        float v[8];
#pragma unroll
        for (int j = 0; j < 4; j++) unpack2(acc[i][j], v[j * 2], v[j * 2 + 1]);
#pragma unroll
        for (int j = 0; j < 8; j++)
            g_xpre[base + j] = v[j] + bias[j0 + tx * 8 + j];
    }
}

// ---------------------------------------------------------------------------
// Persistent GRU recurrence: 128 CTAs, each owns BN=8 hidden columns x 3 gates.
// Weights resident in SMEM for all 512 steps; grid barrier between steps.
// 256 threads = 128 m-groups (2 rows) x 2 n-groups (4 cols), FFMA2 inner loop.
__global__ void __launch_bounds__(256, 1)
gru_persistent_kernel(const float* __restrict__ Whr, const float* __restrict__ bhr,
                      const float* __restrict__ Whc, const float* __restrict__ bhc,
                      const float* __restrict__ Whz, const float* __restrict__ bhz) {
    extern __shared__ float smem[];
    float* Ws = smem;                       // [3][HID][BN]  (k-major per gate)
    float* Hs = smem + WS_ELEMS;            // [2][BK][HS_PITCH]

    const int tid = threadIdx.x;
    const int n0  = blockIdx.x * BN;
    const int tm  = tid >> 1;               // 0..127 -> rows tm*2, tm*2+1
    const int tn  = tid & 1;                // 0..1   -> cols n0 + tn*4 .. +3

    // ---- Load this CTA's weight slice once: Ws[g][k][j] = Wg[n0+j][k] ----
    {
        const float* __restrict__ Wg[3] = {Whr, Whc, Whz};
#pragma unroll
        for (int g = 0; g < 3; g++) {
            for (int v = 0; v < 8; v++) {
                int idx = v * 256 + tid;        // float4 index, 0..2047
                int j  = idx >> 8;              // 0..7
                int kq = idx & 255;
                float4 w = *(const float4*)(Wg[g] + (size_t)(n0 + j) * HID + kq * 4);
                float* dst = Ws + ((size_t)(g << 10) + kq * 4) * BN + j;
                dst[0 * BN] = w.x;
                dst[1 * BN] = w.y;
                dst[2 * BN] = w.z;
                dst[3 * BN] = w.w;
            }
        }
    }

    // ---- Per-thread recurrent biases (constant across steps) ----
    float bR[4], bC[4], bZ[4];
#pragma unroll
    for (int j = 0; j < 4; j++) {
        int col = n0 + tn * 4 + j;
        bR[j] = bhr[col];
        bC[j] = bhc[col];
        bZ[j] = bhz[col];
    }
    __syncthreads();

    const u64* __restrict__ w0 = (const u64*)(Ws + 0 * HID * BN + tn * 4);
    const u64* __restrict__ w1 = (const u64*)(Ws + 1 * HID * BN + tn * 4);
    const u64* __restrict__ w2 = (const u64*)(Ws + 2 * HID * BN + tn * 4);

    for (int t = 0; t < Tlen; t++) {
        const float* __restrict__ hprev = g_h[t & 1];
        float* __restrict__ hnext = g_h[(t & 1) ^ 1];

        // ---- prefetch epilogue operands early (latency fully hidden) ----
        float4 pxr[2], pxc[2], pxz[2], pho[2];
#pragma unroll
        for (int m = 0; m < 2; m++) {
            const int b = tm * 2 + m;
            const size_t xb = ((size_t)t * Bsz + b) * G3 + n0 + tn * 4;
            pxr[m] = __ldcg((const float4*)(g_xpre + xb));
            pxc[m] = __ldcg((const float4*)(g_xpre + xb + HID));
            pxz[m] = __ldcg((const float4*)(g_xpre + xb + 2 * HID));
            pho[m] = __ldcg((const float4*)(hprev + (size_t)b * HID + n0 + tn * 4));
        }

        u64 acc[3][2][2];
#pragma unroll
        for (int g = 0; g < 3; g++)
#pragma unroll
            for (int m = 0; m < 2; m++) { acc[g][m][0] = 0ull; acc[g][m][1] = 0ull; }

        // stage chunk 0 of hprev into smem (transposed, k-major)
        float4 st[8];
#pragma unroll
        for (int p = 0; p < 8; p++) {
            int i = p * 256 + tid;
            int b = i >> 3, kq = i & 7;
            st[p] = __ldcg((const float4*)(hprev + (size_t)b * HID + kq * 4));
        }
#pragma unroll
        for (int p = 0; p < 8; p++) {
            int i = p * 256 + tid;
            int b = i >> 3, kq = i & 7;
            Hs[(kq * 4 + 0) * HS_PITCH + b] = st[p].x;
            Hs[(kq * 4 + 1) * HS_PITCH + b] = st[p].y;
            Hs[(kq * 4 + 2) * HS_PITCH + b] = st[p].z;
            Hs[(kq * 4 + 3) * HS_PITCH + b] = st[p].w;
        }
        __syncthreads();

        for (int kc = 0; kc < HID / BK; kc++) {
            // issue next-chunk global loads early
            if (kc < HID / BK - 1) {
#pragma unroll
                for (int p = 0; p < 8; p++) {
                    int i = p * 256 + tid;
                    int b = i >> 3, kq = i & 7;
                    st[p] = __ldcg((const float4*)(hprev + (size_t)b * HID +
                                                   (kc + 1) * BK + kq * 4));
                }
            }

            const float* hs = Hs + (size_t)(kc & 1) * HS_ELEMS + tm * 2;
            const int kb = kc * BK;
#pragma unroll
            for (int k = 0; k < BK; k++) {
                float2 hv = *(const float2*)(hs + k * HS_PITCH);
                u64 h0 = pack2(hv.x, hv.x);
                u64 h1 = pack2(hv.y, hv.y);
                const size_t wk = (size_t)(kb + k) * (BN / 2);
                u64 wa0 = w0[wk], wa1 = w0[wk + 1];
                u64 wb0 = w1[wk], wb1 = w1[wk + 1];
                u64 wc0 = w2[wk], wc1 = w2[wk + 1];
                acc[0][0][0] = fma2(h0, wa0, acc[0][0][0]);
                acc[0][0][1] = fma2(h0, wa1, acc[0][0][1]);
                acc[0][1][0] = fma2(h1, wa0, acc[0][1][0]);
                acc[0][1][1] = fma2(h1, wa1, acc[0][1][1]);
                acc[1][0][0] = fma2(h0, wb0, acc[1][0][0]);
                acc[1][0][1] = fma2(h0, wb1, acc[1][0][1]);
                acc[1][1][0] = fma2(h1, wb0, acc[1][1][0]);
                acc[1][1][1] = fma2(h1, wb1, acc[1][1][1]);
                acc[2][0][0] = fma2(h0, wc0, acc[2][0][0]);
                acc[2][0][1] = fma2(h0, wc1, acc[2][0][1]);
                acc[2][1][0] = fma2(h1, wc0, acc[2][1][0]);
                acc[2][1][1] = fma2(h1, wc1, acc[2][1][1]);
            }

            if (kc < HID / BK - 1) {
                float* dst = Hs + (size_t)((kc + 1) & 1) * HS_ELEMS;
#pragma unroll
                for (int p = 0; p < 8; p++) {
                    int i = p * 256 + tid;
                    int b = i >> 3, kq = i & 7;
                    dst[(kq * 4 + 0) * HS_PITCH + b] = st[p].x;
                    dst[(kq * 4 + 1) * HS_PITCH + b] = st[p].y;
                    dst[(kq * 4 + 2) * HS_PITCH + b] = st[p].z;
                    dst[(kq * 4 + 3) * HS_PITCH + b] = st[p].w;
                }
            }
            __syncthreads();
        }

        // ---- fused GRU elementwise update for this thread's 2x4 outputs ----
#pragma unroll
        for (int m = 0; m < 2; m++) {
            const int b = tm * 2 + m;
            float ar[4], ac_[4], az[4];
            unpack2(acc[0][m][0], ar[0], ar[1]);  unpack2(acc[0][m][1], ar[2], ar[3]);
            unpack2(acc[1][m][0], ac_[0], ac_[1]); unpack2(acc[1][m][1], ac_[2], ac_[3]);
            unpack2(acc[2][m][0], az[0], az[1]);  unpack2(acc[2][m][1], az[2], az[3]);

            float xr[4] = {pxr[m].x, pxr[m].y, pxr[m].z, pxr[m].w};
            float xc[4] = {pxc[m].x, pxc[m].y, pxc[m].z, pxc[m].w};
            float xz[4] = {pxz[m].x, pxz[m].y, pxz[m].z, pxz[m].w};
            float ho[4] = {pho[m].x, pho[m].y, pho[m].z, pho[m].w};

            float hn[4];
#pragma unroll
            for (int j = 0; j < 4; j++) {
                float r = sigf(xr[j] + ar[j] + bR[j]);
                float c = tanhf(xc[j] + r * (ac_[j] + bC[j]));
                float z = sigf(xz[j] + az[j] + bZ[j]);
                hn[j] = (1.0f - z) * ho[j] + z * c;
            }
            float4 o; o.x = hn[0]; o.y = hn[1]; o.z = hn[2]; o.w = hn[3];
            *(float4*)(hnext + (size_t)b * HID + n0 + tn * 4) = o;
        }

        // ---- grid barrier (monotonic counter; zeroed by zero_h_kernel) ----
        __syncthreads();
        if (tid == 0) {
            __threadfence();
            atomicAdd(&g_bar, 1u);
            const unsigned target = (unsigned)(t + 1) * (unsigned)gridDim.x;
            volatile unsigned* vb = &g_bar;
            while (*vb < target) __nanosleep(64);
            __threadfence();
        }
        __syncthreads();
    }
}

// ---------------------------------------------------------------------------
// out[b][o] = h_final[b] . Wo[o] + bo[o]   (h_final = g_h[0] after 512 steps)
__global__ void gemm_out_kernel(const float* __restrict__ Wo, const float* __restrict__ bo,
                                float* __restrict__ out) {
    const int BKo = 32;
    __shared__ float HsO[BKo][32];
    __shared__ float WsO[BKo][64];

    const float* __restrict__ h = g_h[0];
    const int n0 = blockIdx.x * 64;
    const int m0 = blockIdx.y * 32;
    const int tid = threadIdx.x;

    const int hr = tid >> 2;
    const int hq = (tid & 3) * 8;
    const int wr = tid >> 1;
    const int wq = (tid & 1) * 16;
    const int tm = tid >> 4;
    const int tn = tid & 15;

    float acc[4][4];
#pragma unroll
    for (int i = 0; i < 4; i++)
#pragma unroll
        for (int j = 0; j < 4; j++) acc[i][j] = 0.f;

    for (int k0 = 0; k0 < HID; k0 += BKo) {
        {
            const float* hp = h + (size_t)(m0 + hr) * HID + k0 + hq;
            float4 h0 = *(const float4*)hp;
            float4 h1 = *(const float4*)(hp + 4);
            HsO[hq + 0][hr] = h0.x; HsO[hq + 1][hr] = h0.y;
            HsO[hq + 2][hr] = h0.z; HsO[hq + 3][hr] = h0.w;
            HsO[hq + 4][hr] = h1.x; HsO[hq + 5][hr] = h1.y;
            HsO[hq + 6][hr] = h1.z; HsO[hq + 7][hr] = h1.w;
        }
        {
            const float* wp = Wo + (size_t)(n0 + wr) * HID + k0 + wq;
#pragma unroll
            for (int u = 0; u < 4; u++) {
                float4 wv = *(const float4*)(wp + u * 4);
                WsO[wq + u * 4 + 0][wr] = wv.x;
                WsO[wq + u * 4 + 1][wr] = wv.y;
                WsO[wq + u * 4 + 2][wr] = wv.z;
                WsO[wq + u * 4 + 3][wr] = wv.w;
            }
        }
        __syncthreads();

#pragma unroll
        for (int k = 0; k < BKo; k++) {
            float4 hv = *(const float4*)&HsO[k][tm * 4];
            float4 wv = *(const float4*)&WsO[k][tn * 4];
            float h4[4] = {hv.x, hv.y, hv.z, hv.w};
            float w4[4] = {wv.x, wv.y, wv.z, wv.w};
#pragma unroll
            for (int i = 0; i < 4; i++)
#pragma unroll
                for (int j = 0; j < 4; j++)
                    acc[i][j] = fmaf(h4[i], w4[j], acc[i][j]);
        }
        __syncthreads();
    }

#pragma unroll
    for (int i = 0; i < 4; i++) {
        const int b = m0 + tm * 4 + i;
#pragma unroll
        for (int j = 0; j < 4; j++) {
            const int o = n0 + tn * 4 + j;
            out[(size_t)b * OUTD + o] = acc[i][j] + bo[o];
        }
    }
}

// ---------------------------------------------------------------------------
extern "C" void kernel_launch(void* const* d_in, const int* in_sizes, int n_in,
                              void* d_out, int out_size) {
    const float* x   = (const float*)d_in[0];
    const float* Wxr = (const float*)d_in[1];
    const float* bxr = (const float*)d_in[2];
    const float* Whr = (const float*)d_in[3];
    const float* bhr = (const float*)d_in[4];
    const float* Wxc = (const float*)d_in[5];
    const float* bxc = (const float*)d_in[6];
    const float* Whc = (const float*)d_in[7];
    const float* bhc = (const float*)d_in[8];
    const float* Wxz = (const float*)d_in[9];
    const float* bxz = (const float*)d_in[10];
    const float* Whz = (const float*)d_in[11];
    const float* bhz = (const float*)d_in[12];
    const float* Wo  = (const float*)d_in[13];
    const float* bo  = (const float*)d_in[14];
    float* out = (float*)d_out;

    cudaFuncSetAttribute(gru_persistent_kernel,
                         cudaFuncAttributeMaxDynamicSharedMemorySize, SMEM_BYTES);

    zero_h_kernel<<<(Bsz * HID + 255) / 256, 256>>>();
    gemm_x_kernel<<<dim3(G3 / 128, (Bsz * Tlen) / 128), 256>>>(x, Wxr, bxr, Wxc, bxc, Wxz, bxz);
    gru_persistent_kernel<<<NCTA, 256, SMEM_BYTES>>>(Whr, bhr, Whc, bhc, Whz, bhz);
    gemm_out_kernel<<<dim3(OUTD / 64, Bsz / 32), 128>>>(Wo, bo, out);
}

// round 8
// speedup vs baseline: 2.4052x; 1.8379x over previous
#include <cuda_runtime.h>
#include <cuda_bf16.h>
#include <math.h>

#define Bsz  256
#define Tlen 512
#define IN   512
#define HID  1024
#define OUTD 512
#define G3   (3 * HID)

#define NCTA   128
#define NTHR   256

// SMEM layout (persistent kernel):
//   Wpack: [3][64][32] uint4  = 98304 B   (B-fragments, hi+lo, packed once)
//   Hs:    [2 buf][2 var][256 row][128 B] = 131072 B  (swizzled bf16 chunks)
#define WP_BYTES   98304
#define HS_OFF     WP_BYTES
#define HS_BUF     65536
#define HS_VAR     32768
#define SMEM_BYTES (WP_BYTES + 2 * HS_BUF)   // 229376 (= 224 KB < 227 KB limit)

// Globals: xpre [T][B][3H] fp32 (~1.6GB), ping-pong h fp32 + bf16 hi/lo, barrier.
__device__ float g_xpre[(size_t)Tlen * Bsz * G3];
__device__ float g_h[2][Bsz * HID];
__device__ unsigned short g_hhi[2][Bsz * HID];
__device__ unsigned short g_hlo[2][Bsz * HID];
__device__ unsigned g_bar;

typedef unsigned int u32;

// ---------------------------------------------------------------------------
__device__ __forceinline__ float sigf(float x) {
    return 1.0f / (1.0f + __expf(-x));
}
// pack {lo half = a, hi half = b} as bf16x2
__device__ __forceinline__ u32 bfpack(float a, float b) {
    u32 r;
    asm("cvt.rn.bf16x2.f32 %0, %1, %2;" : "=r"(r) : "f"(b), "f"(a));
    return r;
}
__device__ __forceinline__ void bfsplit(float x, float& hi, float& lo) {
    __nv_bfloat16 h = __float2bfloat16_rn(x);
    hi = __bfloat162float(h);
    lo = x - hi;
}
__device__ __forceinline__ void cpa16(u32 dst, const void* src) {
    asm volatile("cp.async.cg.shared.global [%0], [%1], 16;" :: "r"(dst), "l"(src));
}
__device__ __forceinline__ void ldm_x4(u32* r, u32 addr) {
    asm volatile("ldmatrix.sync.aligned.m8n8.x4.shared.b16 {%0,%1,%2,%3}, [%4];"
                 : "=r"(r[0]), "=r"(r[1]), "=r"(r[2]), "=r"(r[3]) : "r"(addr));
}
__device__ __forceinline__ void mma_bf16(float* d, const u32* a, u32 b0, u32 b1) {
    asm volatile(
        "mma.sync.aligned.m16n8k16.row.col.f32.bf16.bf16.f32 "
        "{%0,%1,%2,%3}, {%4,%5,%6,%7}, {%8,%9}, {%0,%1,%2,%3};"
        : "+f"(d[0]), "+f"(d[1]), "+f"(d[2]), "+f"(d[3])
        : "r"(a[0]), "r"(a[1]), "r"(a[2]), "r"(a[3]), "r"(b0), "r"(b1));
}

// ---------------------------------------------------------------------------
__global__ void zero_h_kernel() {
    int i = blockIdx.x * blockDim.x + threadIdx.x;
    if (i < Bsz * HID) g_h[0][i] = 0.0f;
    if (i < (Bsz * HID) / 2) {
        ((u32*)g_hhi[0])[i] = 0u;
        ((u32*)g_hlo[0])[i] = 0u;
    }
    if (i == 0) g_bar = 0u;
}

// ---------------------------------------------------------------------------
// X projection: out[t][b][g*H+j] = x[b][t] . Wx_g[j] + bx_g[j]
__global__ void gemm_x_kernel(const float* __restrict__ x,
                              const float* __restrict__ Wxr, const float* __restrict__ bxr,
                              const float* __restrict__ Wxc, const float* __restrict__ bxc,
                              const float* __restrict__ Wxz, const float* __restrict__ bxz) {
    const int BM = 128, BNx = 128, BKx = 8;
    __shared__ float As[BKx][BM];
    __shared__ float Bs[BKx][BNx];

    const int n0 = blockIdx.x * BNx;
    const int m0 = blockIdx.y * BM;
    const int g  = n0 >> 10;
    const float* __restrict__ W    = (g == 0) ? Wxr : ((g == 1) ? Wxc : Wxz);
    const float* __restrict__ bias = (g == 0) ? bxr : ((g == 1) ? bxc : bxz);
    const int j0 = n0 - (g << 10);

    const int tid = threadIdx.x;
    const int a_row = tid >> 1;
    const int a_col = (tid & 1) * 4;
    const int tx = tid & 15;
    const int ty = tid >> 4;

    float acc[8][8];
#pragma unroll
    for (int i = 0; i < 8; i++)
#pragma unroll
        for (int j = 0; j < 8; j++) acc[i][j] = 0.0f;

    for (int k0 = 0; k0 < IN; k0 += BKx) {
        float4 av = *(const float4*)(x + (size_t)(m0 + a_row) * IN + k0 + a_col);
        As[a_col + 0][a_row] = av.x;
        As[a_col + 1][a_row] = av.y;
        As[a_col + 2][a_row] = av.z;
        As[a_col + 3][a_row] = av.w;
        float4 bv = *(const float4*)(W + (size_t)(j0 + a_row) * IN + k0 + a_col);
        Bs[a_col + 0][a_row] = bv.x;
        Bs[a_col + 1][a_row] = bv.y;
        Bs[a_col + 2][a_row] = bv.z;
        Bs[a_col + 3][a_row] = bv.w;
        __syncthreads();

#pragma unroll
        for (int k = 0; k < BKx; k++) {
            float4 a0 = *(const float4*)&As[k][ty * 8];
            float4 a1 = *(const float4*)&As[k][ty * 8 + 4];
            float4 b0 = *(const float4*)&Bs[k][tx * 8];
            float4 b1 = *(const float4*)&Bs[k][tx * 8 + 4];
            float a[8] = {a0.x, a0.y, a0.z, a0.w, a1.x, a1.y, a1.z, a1.w};
            float b[8] = {b0.x, b0.y, b0.z, b0.w, b1.x, b1.y, b1.z, b1.w};
#pragma unroll
            for (int i = 0; i < 8; i++)
#pragma unroll
                for (int j = 0; j < 8; j++)
                    acc[i][j] = fmaf(a[i], b[j], acc[i][j]);
        }
        __syncthreads();
    }

#pragma unroll
    for (int i = 0; i < 8; i++) {
        const int m = m0 + ty * 8 + i;
        const int b = m >> 9;
        const int t = m & (Tlen - 1);
        const size_t base = ((size_t)t * Bsz + b) * G3 + n0;
#pragma unroll
        for (int j = 0; j < 8; j++) {
            const int nl = tx * 8 + j;
            g_xpre[base + nl] = acc[i][j] + bias[j0 + nl];
        }
    }
}

// ---------------------------------------------------------------------------
// Persistent GRU recurrence with bf16-split tensor-core MMA.
// 128 CTAs x 256 threads (8 warps). CTA owns 8 hidden cols x 3 gates.
// Weights fragment-packed in SMEM once; h staged per step via cp.async +
// ldmatrix; grid barrier between steps.
__global__ void __launch_bounds__(NTHR, 1)
gru_persistent_kernel(const float* __restrict__ Whr, const float* __restrict__ bhr,
                      const float* __restrict__ Whc, const float* __restrict__ bhc,
                      const float* __restrict__ Whz, const float* __restrict__ bhz) {
    extern __shared__ unsigned char smem[];
    uint4* Wp = (uint4*)smem;
    const u32 smem_u32 = (u32)__cvta_generic_to_shared(smem);

    const int tid = threadIdx.x;
    const int w   = tid >> 5;
    const int l   = tid & 31;
    const int n0  = blockIdx.x * 8;       // gate-local column base

    // ---- Pack weight B-fragments once: Wp[g][kt][lane] = {bhi0,bhi1,blo0,blo1}
    {
        const float* __restrict__ Wg[3] = {Whr, Whc, Whz};
        for (int e = tid; e < 3 * 64 * 32; e += NTHR) {
            int g = e >> 11, rem = e & 2047;
            int kt = rem >> 5, lane = rem & 31;
            int n  = n0 + (lane >> 2);
            int k0 = kt * 16 + (lane & 3) * 2;
            const float* wr = Wg[g] + (size_t)n * HID + k0;
            float2 wa = *(const float2*)wr;        // k0, k0+1
            float2 wb = *(const float2*)(wr + 8);  // k0+8, k0+9
            float h0, l0, h1, l1, h8, l8, h9, l9;
            bfsplit(wa.x, h0, l0); bfsplit(wa.y, h1, l1);
            bfsplit(wb.x, h8, l8); bfsplit(wb.y, h9, l9);
            Wp[e] = make_uint4(bfpack(h0, h1), bfpack(h8, h9),
                               bfpack(l0, l1), bfpack(l8, l9));
        }
    }

    // ---- per-lane constants ----
    const int col0 = n0 + (l & 3) * 2;          // this lane's column pair
    const float2 bR = *(const float2*)(bhr + col0);
    const float2 bC = *(const float2*)(bhc + col0);
    const float2 bZ = *(const float2*)(bhz + col0);

    // ldmatrix per-lane addressing (canonical x4 16x16 b16 tile)
    const int lrow  = (l & 7) | (((l >> 3) & 1) << 3);   // row within 16
    const int cb    = (l >> 4) * 16;                     // byte-col 0/16
    const int lswz  = (lrow & 7) * 16;                   // swizzle mask

    // epilogue rows: q = mtl*2 + s -> row = (2w+mtl)*16 + (l>>2) + 8s
    int erow[4];
#pragma unroll
    for (int q = 0; q < 4; q++)
        erow[q] = (2 * w + (q >> 1)) * 16 + (l >> 2) + 8 * (q & 1);

    __syncthreads();

    for (int t = 0; t < Tlen; t++) {
        const int hb = t & 1, nb = hb ^ 1;

        // ---- prefetch epilogue operands first (longest latency to hide) ----
        float2 pxr[4], pxc[4], pxz[4], pho[4];
#pragma unroll
        for (int q = 0; q < 4; q++) {
            const size_t xb = ((size_t)t * Bsz + erow[q]) * G3 + col0;
            pxr[q] = *(const float2*)(g_xpre + xb);
            pxc[q] = *(const float2*)(g_xpre + xb + HID);
            pxz[q] = *(const float2*)(g_xpre + xb + 2 * HID);
            pho[q] = *(const float2*)(g_h[hb] + (size_t)erow[q] * HID + col0);
        }

        // ---- stage chunk 0 (cp.async) ----
        {
            const unsigned short* srcs[2] = {g_hhi[hb], g_hlo[hb]};
#pragma unroll
            for (int p = 0; p < 16; p++) {
                int i = p * NTHR + tid;
                int var = i >> 11, rem = i & 2047;
                int row = rem >> 3, seg = rem & 7;
                const void* src = srcs[var] + (size_t)row * HID + seg * 8;
                u32 dst = smem_u32 + HS_OFF + var * HS_VAR + row * 128 +
                          ((seg ^ (row & 7)) * 16);
                cpa16(dst, src);
            }
            asm volatile("cp.async.commit_group;");
        }

        float acc[3][2][4];
#pragma unroll
        for (int g = 0; g < 3; g++)
#pragma unroll
            for (int m = 0; m < 2; m++)
#pragma unroll
                for (int d = 0; d < 4; d++) acc[g][m][d] = 0.0f;

        for (int kc = 0; kc < 16; kc++) {
            if (kc < 15) {   // stage next chunk
                const unsigned short* srcs[2] = {g_hhi[hb], g_hlo[hb]};
                const int koff = (kc + 1) * 64;
                const int bufo = ((kc + 1) & 1) * HS_BUF;
#pragma unroll
                for (int p = 0; p < 16; p++) {
                    int i = p * NTHR + tid;
                    int var = i >> 11, rem = i & 2047;
                    int row = rem >> 3, seg = rem & 7;
                    const void* src = srcs[var] + (size_t)row * HID + koff + seg * 8;
                    u32 dst = smem_u32 + HS_OFF + bufo + var * HS_VAR + row * 128 +
                              ((seg ^ (row & 7)) * 16);
                    cpa16(dst, src);
                }
                asm volatile("cp.async.commit_group;");
                asm volatile("cp.async.wait_group 1;");
            } else {
                asm volatile("cp.async.wait_group 0;");
            }
            __syncthreads();

            const u32 plane0 = smem_u32 + HS_OFF + (kc & 1) * HS_BUF;
#pragma unroll
            for (int ktl = 0; ktl < 4; ktl++) {
                const int kt = kc * 4 + ktl;
                const u32 koffswz = (u32)((ktl * 32 + cb) ^ lswz);
                u32 Ahi[2][4], Alo[2][4];
#pragma unroll
                for (int mtl = 0; mtl < 2; mtl++) {
                    const int mt = 2 * w + mtl;
                    u32 a = plane0 + mt * 2048 + lrow * 128 + koffswz;
                    ldm_x4(Ahi[mtl], a);
                    ldm_x4(Alo[mtl], a + HS_VAR);
                }
#pragma unroll
                for (int g = 0; g < 3; g++) {
                    uint4 B = Wp[(g * 64 + kt) * 32 + l];
#pragma unroll
                    for (int mtl = 0; mtl < 2; mtl++) {
                        mma_bf16(acc[g][mtl], Ahi[mtl], B.x, B.y);   // hh
                        mma_bf16(acc[g][mtl], Ahi[mtl], B.z, B.w);   // hi*lo
                        mma_bf16(acc[g][mtl], Alo[mtl], B.x, B.y);   // lo*hi
                    }
                }
            }
            __syncthreads();
        }

        // ---- fused GRU elementwise update: 4 (row, colpair) per lane ----
#pragma unroll
        for (int q = 0; q < 4; q++) {
            const int mtl = q >> 1, s = q & 1;
            const int d0 = s * 2;
            float aR0 = acc[0][mtl][d0],     aR1 = acc[0][mtl][d0 + 1];
            float aC0 = acc[1][mtl][d0],     aC1 = acc[1][mtl][d0 + 1];
            float aZ0 = acc[2][mtl][d0],     aZ1 = acc[2][mtl][d0 + 1];

            float r0 = sigf(pxr[q].x + aR0 + bR.x);
            float r1 = sigf(pxr[q].y + aR1 + bR.y);
            float c0 = tanhf(pxc[q].x + r0 * (aC0 + bC.x));
            float c1 = tanhf(pxc[q].y + r1 * (aC1 + bC.y));
            float z0 = sigf(pxz[q].x + aZ0 + bZ.x);
            float z1 = sigf(pxz[q].y + aZ1 + bZ.y);
            float hn0 = (1.0f - z0) * pho[q].x + z0 * c0;
            float hn1 = (1.0f - z1) * pho[q].y + z1 * c1;

            const size_t hb_off = (size_t)erow[q] * HID + col0;
            float2 hv; hv.x = hn0; hv.y = hn1;
            *(float2*)(g_h[nb] + hb_off) = hv;

            float h0f, l0f, h1f, l1f;
            bfsplit(hn0, h0f, l0f);
            bfsplit(hn1, h1f, l1f);
            ((u32*)g_hhi[nb])[hb_off >> 1] = bfpack(h0f, h1f);
            ((u32*)g_hlo[nb])[hb_off >> 1] = bfpack(l0f, l1f);
        }

        // ---- grid barrier (monotonic counter; zeroed in-stream each launch) ----
        __syncthreads();
        if (tid == 0) {
            __threadfence();
            atomicAdd(&g_bar, 1u);
            const unsigned target = (unsigned)(t + 1) * (unsigned)gridDim.x;
            volatile unsigned* vb = &g_bar;
            while (*vb < target) __nanosleep(64);
            __threadfence();
        }
        __syncthreads();
    }
}

// ---------------------------------------------------------------------------
// out[b][o] = h_final[b] . Wo[o] + bo[o]   (h_final = g_h[0] after 512 steps)
__global__ void gemm_out_kernel(const float* __restrict__ Wo, const float* __restrict__ bo,
                                float* __restrict__ out) {
    const int BKo = 32;
    __shared__ float HsO[BKo][32];
    __shared__ float WsO[BKo][64];

    const float* __restrict__ h = g_h[0];
    const int n0 = blockIdx.x * 64;
    const int m0 = blockIdx.y * 32;
    const int tid = threadIdx.x;

    const int hr = tid >> 2;
    const int hq = (tid & 3) * 8;
    const int wr = tid >> 1;
    const int wq = (tid & 1) * 16;
    const int tm = tid >> 4;
    const int tn = tid & 15;

    float acc[4][4];
#pragma unroll
    for (int i = 0; i < 4; i++)
#pragma unroll
        for (int j = 0; j < 4; j++) acc[i][j] = 0.f;

    for (int k0 = 0; k0 < HID; k0 += BKo) {
        {
            const float* hp = h + (size_t)(m0 + hr) * HID + k0 + hq;
            float4 h0 = *(const float4*)hp;
            float4 h1 = *(const float4*)(hp + 4);
            HsO[hq + 0][hr] = h0.x; HsO[hq + 1][hr] = h0.y;
            HsO[hq + 2][hr] = h0.z; HsO[hq + 3][hr] = h0.w;
            HsO[hq + 4][hr] = h1.x; HsO[hq + 5][hr] = h1.y;
            HsO[hq + 6][hr] = h1.z; HsO[hq + 7][hr] = h1.w;
        }
        {
            const float* wp = Wo + (size_t)(n0 + wr) * HID + k0 + wq;
#pragma unroll
            for (int u = 0; u < 4; u++) {
                float4 wv = *(const float4*)(wp + u * 4);
                WsO[wq + u * 4 + 0][wr] = wv.x;
                WsO[wq + u * 4 + 1][wr] = wv.y;
                WsO[wq + u * 4 + 2][wr] = wv.z;
                WsO[wq + u * 4 + 3][wr] = wv.w;
            }
        }
        __syncthreads();

#pragma unroll
        for (int k = 0; k < BKo; k++) {
            float4 hv = *(const float4*)&HsO[k][tm * 4];
            float4 wv = *(const float4*)&WsO[k][tn * 4];
            float h4[4] = {hv.x, hv.y, hv.z, hv.w};
            float w4[4] = {wv.x, wv.y, wv.z, wv.w};
#pragma unroll
            for (int i = 0; i < 4; i++)
#pragma unroll
                for (int j = 0; j < 4; j++)
                    acc[i][j] = fmaf(h4[i], w4[j], acc[i][j]);
        }
        __syncthreads();
    }

#pragma unroll
    for (int i = 0; i < 4; i++) {
        const int b = m0 + tm * 4 + i;
#pragma unroll
        for (int j = 0; j < 4; j++) {
            const int o = n0 + tn * 4 + j;
            out[(size_t)b * OUTD + o] = acc[i][j] + bo[o];
        }
    }
}

// ---------------------------------------------------------------------------
extern "C" void kernel_launch(void* const* d_in, const int* in_sizes, int n_in,
                              void* d_out, int out_size) {
    const float* x   = (const float*)d_in[0];
    const float* Wxr = (const float*)d_in[1];
    const float* bxr = (const float*)d_in[2];
    const float* Whr = (const float*)d_in[3];
    const float* bhr = (const float*)d_in[4];
    const float* Wxc = (const float*)d_in[5];
    const float* bxc = (const float*)d_in[6];
    const float* Whc = (const float*)d_in[7];
    const float* bhc = (const float*)d_in[8];
    const float* Wxz = (const float*)d_in[9];
    const float* bxz = (const float*)d_in[10];
    const float* Whz = (const float*)d_in[11];
    const float* bhz = (const float*)d_in[12];
    const float* Wo  = (const float*)d_in[13];
    const float* bo  = (const float*)d_in[14];
    float* out = (float*)d_out;

    cudaFuncSetAttribute(gru_persistent_kernel,
                         cudaFuncAttributeMaxDynamicSharedMemorySize, SMEM_BYTES);

    zero_h_kernel<<<(Bsz * HID + 255) / 256, 256>>>();
    gemm_x_kernel<<<dim3(G3 / 128, (Bsz * Tlen) / 128), 256>>>(x, Wxr, bxr, Wxc, bxc, Wxz, bxz);
    gru_persistent_kernel<<<NCTA, NTHR, SMEM_BYTES>>>(Whr, bhr, Whc, bhc, Whz, bhz);
    gemm_out_kernel<<<dim3(OUTD / 64, Bsz / 32), 128>>>(Wo, bo, out);
}

// round 12
// speedup vs baseline: 3.6292x; 1.5089x over previous
#include <cuda_runtime.h>
#include <cuda_bf16.h>
#include <math.h>

#define Bsz  256
#define Tlen 512
#define IN   512
#define HID  1024
#define OUTD 512
#define G3   (3 * HID)

#define NCTA   128
#define NTHR   256

// ---- persistent-kernel SMEM layout ----
#define WP_BYTES   98304
#define HS_OFF     WP_BYTES
#define HS_BUF     65536
#define HS_VAR     32768
#define SMEM_BYTES (WP_BYTES + 2 * HS_BUF)   // 229376

// ---- gemm_x_mma SMEM layout: A [2buf][2var][128r][128B], B same ----
#define XA_VAR   16384
#define XA_BUF   32768
#define XB_OFF   65536
#define XSMEM    131072

// Globals
__device__ float g_xpre[(size_t)Tlen * Bsz * G3];
__device__ float g_h[2][Bsz * HID];
__device__ unsigned short g_hhi[2][Bsz * HID];
__device__ unsigned short g_hlo[2][Bsz * HID];
__device__ unsigned short g_xhi[(size_t)Bsz * Tlen * IN];
__device__ unsigned short g_xlo[(size_t)Bsz * Tlen * IN];
__device__ unsigned short g_wxhi[(size_t)G3 * IN];
__device__ unsigned short g_wxlo[(size_t)G3 * IN];
__device__ float g_bxcat[G3];
__device__ unsigned g_bar;

typedef unsigned int u32;

// ---------------------------------------------------------------------------
__device__ __forceinline__ float sigf(float x) {
    return 1.0f / (1.0f + __expf(-x));
}
__device__ __forceinline__ u32 bfpack(float a, float b) {   // lo half=a, hi half=b
    u32 r;
    asm("cvt.rn.bf16x2.f32 %0, %1, %2;" : "=r"(r) : "f"(b), "f"(a));
    return r;
}
__device__ __forceinline__ void bfsplit(float x, float& hi, float& lo) {
    __nv_bfloat16 h = __float2bfloat16_rn(x);
    hi = __bfloat162float(h);
    lo = x - hi;
}
__device__ __forceinline__ void cpa16(u32 dst, const void* src) {
    asm volatile("cp.async.cg.shared.global [%0], [%1], 16;" :: "r"(dst), "l"(src));
}
__device__ __forceinline__ void ldm_x4(u32* r, u32 addr) {
    asm volatile("ldmatrix.sync.aligned.m8n8.x4.shared.b16 {%0,%1,%2,%3}, [%4];"
                 : "=r"(r[0]), "=r"(r[1]), "=r"(r[2]), "=r"(r[3]) : "r"(addr));
}
__device__ __forceinline__ void mma_bf16(float* d, const u32* a, u32 b0, u32 b1) {
    asm volatile(
        "mma.sync.aligned.m16n8k16.row.col.f32.bf16.bf16.f32 "
        "{%0,%1,%2,%3}, {%4,%5,%6,%7}, {%8,%9}, {%0,%1,%2,%3};"
        : "+f"(d[0]), "+f"(d[1]), "+f"(d[2]), "+f"(d[3])
        : "r"(a[0]), "r"(a[1]), "r"(a[2]), "r"(a[3]), "r"(b0), "r"(b1));
}

// ---------------------------------------------------------------------------
__global__ void zero_h_kernel() {
    int i = blockIdx.x * blockDim.x + threadIdx.x;
    if (i < Bsz * HID) g_h[0][i] = 0.0f;
    if (i < (Bsz * HID) / 2) {
        ((u32*)g_hhi[0])[i] = 0u;
        ((u32*)g_hlo[0])[i] = 0u;
    }
    if (i == 0) g_bar = 0u;
}

// ---------------------------------------------------------------------------
// Prep: split x into bf16 hi/lo (4 floats per thread).
__global__ void split_x_kernel(const float* __restrict__ x) {
    size_t i4 = (size_t)blockIdx.x * blockDim.x + threadIdx.x;
    const size_t n4 = (size_t)Bsz * Tlen * IN / 4;
    if (i4 >= n4) return;
    float4 v = *(const float4*)(x + i4 * 4);
    float h0, l0, h1, l1, h2, l2, h3, l3;
    bfsplit(v.x, h0, l0); bfsplit(v.y, h1, l1);
    bfsplit(v.z, h2, l2); bfsplit(v.w, h3, l3);
    ((u32*)g_xhi)[i4 * 2 + 0] = bfpack(h0, h1);
    ((u32*)g_xhi)[i4 * 2 + 1] = bfpack(h2, h3);
    ((u32*)g_xlo)[i4 * 2 + 0] = bfpack(l0, l1);
    ((u32*)g_xlo)[i4 * 2 + 1] = bfpack(l2, l3);
}

// Prep: split + concatenate Wx gates into [3072][512] hi/lo; concat biases.
__global__ void split_w_kernel(const float* __restrict__ Wxr, const float* __restrict__ Wxc,
                               const float* __restrict__ Wxz,
                               const float* __restrict__ bxr, const float* __restrict__ bxc,
                               const float* __restrict__ bxz) {
    int i4 = blockIdx.x * blockDim.x + threadIdx.x;
    if (i4 < G3 * IN / 4) {
        int n = i4 >> 7;                  // row (0..3071); 128 float4 per row
        int kq = i4 & 127;
        int g = n >> 10, j = n & 1023;
        const float* W = (g == 0) ? Wxr : ((g == 1) ? Wxc : Wxz);
        float4 v = *(const float4*)(W + (size_t)j * IN + kq * 4);
        float h0, l0, h1, l1, h2, l2, h3, l3;
        bfsplit(v.x, h0, l0); bfsplit(v.y, h1, l1);
        bfsplit(v.z, h2, l2); bfsplit(v.w, h3, l3);
        ((u32*)g_wxhi)[i4 * 2 + 0] = bfpack(h0, h1);
        ((u32*)g_wxhi)[i4 * 2 + 1] = bfpack(h2, h3);
        ((u32*)g_wxlo)[i4 * 2 + 0] = bfpack(l0, l1);
        ((u32*)g_wxlo)[i4 * 2 + 1] = bfpack(l2, l3);
    }
    if (i4 < G3) {
        int g = i4 >> 10, j = i4 & 1023;
        g_bxcat[i4] = ((g == 0) ? bxr : ((g == 1) ? bxc : bxz))[j];
    }
}

// ---------------------------------------------------------------------------
// X projection via bf16-split tensor cores.
// Grid (24 n-blocks, 1024 m-blocks), 256 thr = 8 warps (4m x 2n), warp 32x64.
// xpre[t][b][n] = x[m=b*T+t] . Wcat[n] + bcat[n]
__global__ void __launch_bounds__(NTHR, 1)
gemm_x_mma_kernel() {
    extern __shared__ unsigned char smem[];
    const u32 sb = (u32)__cvta_generic_to_shared(smem);

    const int tid = threadIdx.x;
    const int w = tid >> 5, l = tid & 31;
    const int n0 = blockIdx.x * 128;
    const int m0 = blockIdx.y * 128;
    const int wm = w >> 1, wn = w & 1;

    // A-ldmatrix lane addressing (16x16 b16, x4)
    const int lrow = (l & 7) | (((l >> 3) & 1) << 3);
    const int cb   = (l >> 4) * 16;
    const int lswz = (lrow & 7) * 16;
    // B-ldmatrix lane addressing (16n x 16k, x4)
    const int brow = (l & 7) | ((l >> 4) << 3);
    const int bsg  = ((l >> 3) & 1) * 16;
    const int bswz = (l & 7) * 16;

    // bias registers: col pair per n-tile
    const int colp = (l & 3) * 2;
    float2 bias[8];
#pragma unroll
    for (int nt = 0; nt < 8; nt++)
        bias[nt] = *(const float2*)(g_bxcat + n0 + wn * 64 + nt * 8 + colp);

    float acc[2][8][4];
#pragma unroll
    for (int i = 0; i < 2; i++)
#pragma unroll
        for (int j = 0; j < 8; j++)
#pragma unroll
            for (int d = 0; d < 4; d++) acc[i][j][d] = 0.0f;

    auto stage = [&](int kc, int buf) {
#pragma unroll
        for (int p = 0; p < 4; p++) {
            int i = p * NTHR + tid;          // 0..1023
            int row = i >> 3, seg = i & 7;
            u32 sw = (u32)((seg ^ (row & 7)) * 16);
            const size_t asrc = (size_t)(m0 + row) * IN + kc * 64 + seg * 8;
            cpa16(sb + buf * XA_BUF + row * 128 + sw, g_xhi + asrc);
            cpa16(sb + buf * XA_BUF + XA_VAR + row * 128 + sw, g_xlo + asrc);
            const size_t bsrc = (size_t)(n0 + row) * IN + kc * 64 + seg * 8;
            cpa16(sb + XB_OFF + buf * XA_BUF + row * 128 + sw, g_wxhi + bsrc);
            cpa16(sb + XB_OFF + buf * XA_BUF + XA_VAR + row * 128 + sw, g_wxlo + bsrc);
        }
    };

    stage(0, 0);
    asm volatile("cp.async.commit_group;");

    for (int kc = 0; kc < 8; kc++) {
        if (kc < 7) {
            stage(kc + 1, (kc + 1) & 1);
            asm volatile("cp.async.commit_group;");
            asm volatile("cp.async.wait_group 1;");
        } else {
            asm volatile("cp.async.wait_group 0;");
        }
        __syncthreads();

        const u32 Ap = sb + (kc & 1) * XA_BUF;
        const u32 Bp = sb + XB_OFF + (kc & 1) * XA_BUF;
#pragma unroll
        for (int ktl = 0; ktl < 4; ktl++) {
            u32 Ahi[2][4], Alo[2][4];
#pragma unroll
            for (int mtl = 0; mtl < 2; mtl++) {
                u32 a = Ap + (wm * 32 + mtl * 16 + lrow) * 128 +
                        (u32)((ktl * 32 + cb) ^ lswz);
                ldm_x4(Ahi[mtl], a);
                ldm_x4(Alo[mtl], a + XA_VAR);
            }
#pragma unroll
            for (int pair = 0; pair < 4; pair++) {
                u32 Bhi[4], Blo[4];
                u32 ba = Bp + (wn * 64 + pair * 16 + brow) * 128 +
                         (u32)((ktl * 32 + bsg) ^ bswz);
                ldm_x4(Bhi, ba);
                ldm_x4(Blo, ba + XA_VAR);
#pragma unroll
                for (int half = 0; half < 2; half++) {
                    u32 bh0 = Bhi[half * 2], bh1 = Bhi[half * 2 + 1];
                    u32 bl0 = Blo[half * 2], bl1 = Blo[half * 2 + 1];
                    const int nt = pair * 2 + half;
#pragma unroll
                    for (int mtl = 0; mtl < 2; mtl++) {
                        mma_bf16(acc[mtl][nt], Ahi[mtl], bh0, bh1);   // hh
                        mma_bf16(acc[mtl][nt], Ahi[mtl], bl0, bl1);   // h*lo
                        mma_bf16(acc[mtl][nt], Alo[mtl], bh0, bh1);   // lo*h
                    }
                }
            }
        }
        __syncthreads();
    }

    // epilogue: write xpre with [t][b][n] layout, add bias
#pragma unroll
    for (int mtl = 0; mtl < 2; mtl++) {
        const int r0 = m0 + wm * 32 + mtl * 16 + (l >> 2);
        const int b0 = r0 >> 9, t0 = r0 & (Tlen - 1);
        const int r1 = r0 + 8;
        const int b1 = r1 >> 9, t1 = r1 & (Tlen - 1);
        const size_t base0 = ((size_t)t0 * Bsz + b0) * G3 + n0 + wn * 64 + colp;
        const size_t base1 = ((size_t)t1 * Bsz + b1) * G3 + n0 + wn * 64 + colp;
#pragma unroll
        for (int nt = 0; nt < 8; nt++) {
            float2 o0, o1;
            o0.x = acc[mtl][nt][0] + bias[nt].x;
            o0.y = acc[mtl][nt][1] + bias[nt].y;
            o1.x = acc[mtl][nt][2] + bias[nt].x;
            o1.y = acc[mtl][nt][3] + bias[nt].y;
            *(float2*)(g_xpre + base0 + nt * 8) = o0;
            *(float2*)(g_xpre + base1 + nt * 8) = o1;
        }
    }
}

// ---------------------------------------------------------------------------
// Persistent GRU recurrence with bf16-split tensor-core MMA (proven in R8).
__global__ void __launch_bounds__(NTHR, 1)
gru_persistent_kernel(const float* __restrict__ Whr, const float* __restrict__ bhr,
                      const float* __restrict__ Whc, const float* __restrict__ bhc,
                      const float* __restrict__ Whz, const float* __restrict__ bhz) {
    extern __shared__ unsigned char smem[];
    uint4* Wp = (uint4*)smem;
    const u32 smem_u32 = (u32)__cvta_generic_to_shared(smem);

    const int tid = threadIdx.x;
    const int w   = tid >> 5;
    const int l   = tid & 31;
    const int n0  = blockIdx.x * 8;

    {
        const float* __restrict__ Wg[3] = {Whr, Whc, Whz};
        for (int e = tid; e < 3 * 64 * 32; e += NTHR) {
            int g = e >> 11, rem = e & 2047;
            int kt = rem >> 5, lane = rem & 31;
            int n  = n0 + (lane >> 2);
            int k0 = kt * 16 + (lane & 3) * 2;
            const float* wr = Wg[g] + (size_t)n * HID + k0;
            float2 wa = *(const float2*)wr;
            float2 wb = *(const float2*)(wr + 8);
            float h0, l0, h1, l1, h8, l8, h9, l9;
            bfsplit(wa.x, h0, l0); bfsplit(wa.y, h1, l1);
            bfsplit(wb.x, h8, l8); bfsplit(wb.y, h9, l9);
            Wp[e] = make_uint4(bfpack(h0, h1), bfpack(h8, h9),
                               bfpack(l0, l1), bfpack(l8, l9));
        }
    }

    const int col0 = n0 + (l & 3) * 2;
    const float2 bR = *(const float2*)(bhr + col0);
    const float2 bC = *(const float2*)(bhc + col0);
    const float2 bZ = *(const float2*)(bhz + col0);

    const int lrow  = (l & 7) | (((l >> 3) & 1) << 3);
    const int cb    = (l >> 4) * 16;
    const int lswz  = (lrow & 7) * 16;

    int erow[4];
#pragma unroll
    for (int q = 0; q < 4; q++)
        erow[q] = (2 * w + (q >> 1)) * 16 + (l >> 2) + 8 * (q & 1);

    __syncthreads();

    for (int t = 0; t < Tlen; t++) {
        const int hb = t & 1, nb = hb ^ 1;

        float2 pxr[4], pxc[4], pxz[4], pho[4];
#pragma unroll
        for (int q = 0; q < 4; q++) {
            const size_t xb = ((size_t)t * Bsz + erow[q]) * G3 + col0;
            pxr[q] = *(const float2*)(g_xpre + xb);
            pxc[q] = *(const float2*)(g_xpre + xb + HID);
            pxz[q] = *(const float2*)(g_xpre + xb + 2 * HID);
            pho[q] = *(const float2*)(g_h[hb] + (size_t)erow[q] * HID + col0);
        }

        {
            const unsigned short* srcs[2] = {g_hhi[hb], g_hlo[hb]};
#pragma unroll
            for (int p = 0; p < 16; p++) {
                int i = p * NTHR + tid;
                int var = i >> 11, rem = i & 2047;
                int row = rem >> 3, seg = rem & 7;
                const void* src = srcs[var] + (size_t)row * HID + seg * 8;
                u32 dst = smem_u32 + HS_OFF + var * HS_VAR + row * 128 +
                          ((seg ^ (row & 7)) * 16);
                cpa16(dst, src);
            }
            asm volatile("cp.async.commit_group;");
        }

        float acc[3][2][4];
#pragma unroll
        for (int g = 0; g < 3; g++)
#pragma unroll
            for (int m = 0; m < 2; m++)
#pragma unroll
                for (int d = 0; d < 4; d++) acc[g][m][d] = 0.0f;

        for (int kc = 0; kc < 16; kc++) {
            if (kc < 15) {
                const unsigned short* srcs[2] = {g_hhi[hb], g_hlo[hb]};
                const int koff = (kc + 1) * 64;
                const int bufo = ((kc + 1) & 1) * HS_BUF;
#pragma unroll
                for (int p = 0; p < 16; p++) {
                    int i = p * NTHR + tid;
                    int var = i >> 11, rem = i & 2047;
                    int row = rem >> 3, seg = rem & 7;
                    const void* src = srcs[var] + (size_t)row * HID + koff + seg * 8;
                    u32 dst = smem_u32 + HS_OFF + bufo + var * HS_VAR + row * 128 +
                              ((seg ^ (row & 7)) * 16);
                    cpa16(dst, src);
                }
                asm volatile("cp.async.commit_group;");
                asm volatile("cp.async.wait_group 1;");
            } else {
                asm volatile("cp.async.wait_group 0;");
            }
            __syncthreads();

            const u32 plane0 = smem_u32 + HS_OFF + (kc & 1) * HS_BUF;
#pragma unroll
            for (int ktl = 0; ktl < 4; ktl++) {
                const int kt = kc * 4 + ktl;
                const u32 koffswz = (u32)((ktl * 32 + cb) ^ lswz);
                u32 Ahi[2][4], Alo[2][4];
#pragma unroll
                for (int mtl = 0; mtl < 2; mtl++) {
                    const int mt = 2 * w + mtl;
                    u32 a = plane0 + mt * 2048 + lrow * 128 + koffswz;
                    ldm_x4(Ahi[mtl], a);
                    ldm_x4(Alo[mtl], a + HS_VAR);
                }
#pragma unroll
                for (int g = 0; g < 3; g++) {
                    uint4 B = Wp[(g * 64 + kt) * 32 + l];
#pragma unroll
                    for (int mtl = 0; mtl < 2; mtl++) {
                        mma_bf16(acc[g][mtl], Ahi[mtl], B.x, B.y);
                        mma_bf16(acc[g][mtl], Ahi[mtl], B.z, B.w);
                        mma_bf16(acc[g][mtl], Alo[mtl], B.x, B.y);
                    }
                }
            }
            __syncthreads();
        }

#pragma unroll
        for (int q = 0; q < 4; q++) {
            const int mtl = q >> 1, s = q & 1;
            const int d0 = s * 2;
            float aR0 = acc[0][mtl][d0],  aR1 = acc[0][mtl][d0 + 1];
            float aC0 = acc[1][mtl][d0],  aC1 = acc[1][mtl][d0 + 1];
            float aZ0 = acc[2][mtl][d0],  aZ1 = acc[2][mtl][d0 + 1];

            float r0 = sigf(pxr[q].x + aR0 + bR.x);
            float r1 = sigf(pxr[q].y + aR1 + bR.y);
            float c0 = tanhf(pxc[q].x + r0 * (aC0 + bC.x));
            float c1 = tanhf(pxc[q].y + r1 * (aC1 + bC.y));
            float z0 = sigf(pxz[q].x + aZ0 + bZ.x);
            float z1 = sigf(pxz[q].y + aZ1 + bZ.y);
            float hn0 = (1.0f - z0) * pho[q].x + z0 * c0;
            float hn1 = (1.0f - z1) * pho[q].y + z1 * c1;

            const size_t hb_off = (size_t)erow[q] * HID + col0;
            float2 hv; hv.x = hn0; hv.y = hn1;
            *(float2*)(g_h[nb] + hb_off) = hv;

            float h0f, l0f, h1f, l1f;
            bfsplit(hn0, h0f, l0f);
            bfsplit(hn1, h1f, l1f);
            ((u32*)g_hhi[nb])[hb_off >> 1] = bfpack(h0f, h1f);
            ((u32*)g_hlo[nb])[hb_off >> 1] = bfpack(l0f, l1f);
        }

        __syncthreads();
        if (tid == 0) {
            __threadfence();
            atomicAdd(&g_bar, 1u);
            const unsigned target = (unsigned)(t + 1) * (unsigned)gridDim.x;
            volatile unsigned* vb = &g_bar;
            while (*vb < target) __nanosleep(64);
            __threadfence();
        }
        __syncthreads();
    }
}

// ---------------------------------------------------------------------------
__global__ void gemm_out_kernel(const float* __restrict__ Wo, const float* __restrict__ bo,
                                float* __restrict__ out) {
    const int BKo = 32;
    __shared__ float HsO[BKo][32];
    __shared__ float WsO[BKo][64];

    const float* __restrict__ h = g_h[0];
    const int n0 = blockIdx.x * 64;
    const int m0 = blockIdx.y * 32;
    const int tid = threadIdx.x;

    const int hr = tid >> 2;
    const int hq = (tid & 3) * 8;
    const int wr = tid >> 1;
    const int wq = (tid & 1) * 16;
    const int tm = tid >> 4;
    const int tn = tid & 15;

    float acc[4][4];
#pragma unroll
    for (int i = 0; i < 4; i++)
#pragma unroll
        for (int j = 0; j < 4; j++) acc[i][j] = 0.f;

    for (int k0 = 0; k0 < HID; k0 += BKo) {
        {
            const float* hp = h + (size_t)(m0 + hr) * HID + k0 + hq;
            float4 h0 = *(const float4*)hp;
            float4 h1 = *(const float4*)(hp + 4);
            HsO[hq + 0][hr] = h0.x; HsO[hq + 1][hr] = h0.y;
            HsO[hq + 2][hr] = h0.z; HsO[hq + 3][hr] = h0.w;
            HsO[hq + 4][hr] = h1.x; HsO[hq + 5][hr] = h1.y;
            HsO[hq + 6][hr] = h1.z; HsO[hq + 7][hr] = h1.w;
        }
        {
            const float* wp = Wo + (size_t)(n0 + wr) * HID + k0 + wq;
#pragma unroll
            for (int u = 0; u < 4; u++) {
                float4 wv = *(const float4*)(wp + u * 4);
                WsO[wq + u * 4 + 0][wr] = wv.x;
                WsO[wq + u * 4 + 1][wr] = wv.y;
                WsO[wq + u * 4 + 2][wr] = wv.z;
                WsO[wq + u * 4 + 3][wr] = wv.w;
            }
        }
        __syncthreads();

#pragma unroll
        for (int k = 0; k < BKo; k++) {
            float4 hv = *(const float4*)&HsO[k][tm * 4];
            float4 wv = *(const float4*)&WsO[k][tn * 4];
            float h4[4] = {hv.x, hv.y, hv.z, hv.w};
            float w4[4] = {wv.x, wv.y, wv.z, wv.w};
#pragma unroll
            for (int i = 0; i < 4; i++)
#pragma unroll
                for (int j = 0; j < 4; j++)
                    acc[i][j] = fmaf(h4[i], w4[j], acc[i][j]);
        }
        __syncthreads();
    }

#pragma unroll
    for (int i = 0; i < 4; i++) {
        const int b = m0 + tm * 4 + i;
#pragma unroll
        for (int j = 0; j < 4; j++) {
            const int o = n0 + tn * 4 + j;
            out[(size_t)b * OUTD + o] = acc[i][j] + bo[o];
        }
    }
}

// ---------------------------------------------------------------------------
extern "C" void kernel_launch(void* const* d_in, const int* in_sizes, int n_in,
                              void* d_out, int out_size) {
    const float* x   = (const float*)d_in[0];
    const float* Wxr = (const float*)d_in[1];
    const float* bxr = (const float*)d_in[2];
    const float* Whr = (const float*)d_in[3];
    const float* bhr = (const float*)d_in[4];
    const float* Wxc = (const float*)d_in[5];
    const float* bxc = (const float*)d_in[6];
    const float* Whc = (const float*)d_in[7];
    const float* bhc = (const float*)d_in[8];
    const float* Wxz = (const float*)d_in[9];
    const float* bxz = (const float*)d_in[10];
    const float* Whz = (const float*)d_in[11];
    const float* bhz = (const float*)d_in[12];
    const float* Wo  = (const float*)d_in[13];
    const float* bo  = (const float*)d_in[14];
    float* out = (float*)d_out;

    cudaFuncSetAttribute(gru_persistent_kernel,
                         cudaFuncAttributeMaxDynamicSharedMemorySize, SMEM_BYTES);
    cudaFuncSetAttribute(gemm_x_mma_kernel,
                         cudaFuncAttributeMaxDynamicSharedMemorySize, XSMEM);

    zero_h_kernel<<<(Bsz * HID + 255) / 256, 256>>>();
    split_x_kernel<<<(int)(((size_t)Bsz * Tlen * IN / 4 + 255) / 256), 256>>>(x);
    split_w_kernel<<<(G3 * IN / 4 + 255) / 256, 256>>>(Wxr, Wxc, Wxz, bxr, bxc, bxz);
    gemm_x_mma_kernel<<<dim3(G3 / 128, (Bsz * Tlen) / 128), NTHR, XSMEM>>>();
    gru_persistent_kernel<<<NCTA, NTHR, SMEM_BYTES>>>(Whr, bhr, Whc, bhc, Whz, bhz);
    gemm_out_kernel<<<dim3(OUTD / 64, Bsz / 32), 128>>>(Wo, bo, out);
}

// round 13
// speedup vs baseline: 4.1854x; 1.1533x over previous
#include <cuda_runtime.h>
#include <cuda_bf16.h>
#include <math.h>

#define Bsz  256
#define Tlen 512
#define IN   512
#define HID  1024
#define OUTD 512
#define G3   (3 * HID)

#define NCTA   128
#define NTHR   256

// ---- persistent-kernel SMEM layout (new tiling: 64 n-slices x 2 m-slices) ----
// Wp: [3 gates][64 kt][2 sub][32 lanes] uint4 = 196608 B (16 cols/gate, hi+lo)
// Hs: [8 warps][2 buf][2 var][16 rows][64 B]  = 32768 B  (warp-private chunks)
#define WP_BYTES   196608
#define HS_OFF     WP_BYTES
#define SMEM_BYTES (WP_BYTES + 32768)        // 229376 (proven R8 footprint)

// ---- gemm_x_mma SMEM layout: A [2buf][2var][128r][128B], B same ----
#define XA_VAR   16384
#define XA_BUF   32768
#define XB_OFF   65536
#define XSMEM    131072

// Globals
__device__ float g_xpre[(size_t)Tlen * Bsz * G3];
__device__ float g_h[2][Bsz * HID];
__device__ unsigned short g_hhi[2][Bsz * HID];
__device__ unsigned short g_hlo[2][Bsz * HID];
__device__ unsigned short g_xhi[(size_t)Bsz * Tlen * IN];
__device__ unsigned short g_xlo[(size_t)Bsz * Tlen * IN];
__device__ unsigned short g_wxhi[(size_t)G3 * IN];
__device__ unsigned short g_wxlo[(size_t)G3 * IN];
__device__ float g_bxcat[G3];
__device__ unsigned g_bar;

typedef unsigned int u32;

// ---------------------------------------------------------------------------
__device__ __forceinline__ float sigf(float x) {
    return 1.0f / (1.0f + __expf(-x));
}
__device__ __forceinline__ u32 bfpack(float a, float b) {   // lo half=a, hi half=b
    u32 r;
    asm("cvt.rn.bf16x2.f32 %0, %1, %2;" : "=r"(r) : "f"(b), "f"(a));
    return r;
}
__device__ __forceinline__ void bfsplit(float x, float& hi, float& lo) {
    __nv_bfloat16 h = __float2bfloat16_rn(x);
    hi = __bfloat162float(h);
    lo = x - hi;
}
__device__ __forceinline__ void cpa16(u32 dst, const void* src) {
    asm volatile("cp.async.cg.shared.global [%0], [%1], 16;" :: "r"(dst), "l"(src));
}
__device__ __forceinline__ void ldm_x4(u32* r, u32 addr) {
    asm volatile("ldmatrix.sync.aligned.m8n8.x4.shared.b16 {%0,%1,%2,%3}, [%4];"
                 : "=r"(r[0]), "=r"(r[1]), "=r"(r[2]), "=r"(r[3]) : "r"(addr));
}
__device__ __forceinline__ void mma_bf16(float* d, const u32* a, u32 b0, u32 b1) {
    asm volatile(
        "mma.sync.aligned.m16n8k16.row.col.f32.bf16.bf16.f32 "
        "{%0,%1,%2,%3}, {%4,%5,%6,%7}, {%8,%9}, {%0,%1,%2,%3};"
        : "+f"(d[0]), "+f"(d[1]), "+f"(d[2]), "+f"(d[3])
        : "r"(a[0]), "r"(a[1]), "r"(a[2]), "r"(a[3]), "r"(b0), "r"(b1));
}

// ---------------------------------------------------------------------------
__global__ void zero_h_kernel() {
    int i = blockIdx.x * blockDim.x + threadIdx.x;
    if (i < Bsz * HID) g_h[0][i] = 0.0f;
    if (i < (Bsz * HID) / 2) {
        ((u32*)g_hhi[0])[i] = 0u;
        ((u32*)g_hlo[0])[i] = 0u;
    }
    if (i == 0) g_bar = 0u;
}

// ---------------------------------------------------------------------------
// Prep: split x into bf16 hi/lo (4 floats per thread).
__global__ void split_x_kernel(const float* __restrict__ x) {
    size_t i4 = (size_t)blockIdx.x * blockDim.x + threadIdx.x;
    const size_t n4 = (size_t)Bsz * Tlen * IN / 4;
    if (i4 >= n4) return;
    float4 v = *(const float4*)(x + i4 * 4);
    float h0, l0, h1, l1, h2, l2, h3, l3;
    bfsplit(v.x, h0, l0); bfsplit(v.y, h1, l1);
    bfsplit(v.z, h2, l2); bfsplit(v.w, h3, l3);
    ((u32*)g_xhi)[i4 * 2 + 0] = bfpack(h0, h1);
    ((u32*)g_xhi)[i4 * 2 + 1] = bfpack(h2, h3);
    ((u32*)g_xlo)[i4 * 2 + 0] = bfpack(l0, l1);
    ((u32*)g_xlo)[i4 * 2 + 1] = bfpack(l2, l3);
}

// Prep: split + concatenate Wx gates into [3072][512] hi/lo; concat biases.
__global__ void split_w_kernel(const float* __restrict__ Wxr, const float* __restrict__ Wxc,
                               const float* __restrict__ Wxz,
                               const float* __restrict__ bxr, const float* __restrict__ bxc,
                               const float* __restrict__ bxz) {
    int i4 = blockIdx.x * blockDim.x + threadIdx.x;
    if (i4 < G3 * IN / 4) {
        int n = i4 >> 7;
        int kq = i4 & 127;
        int g = n >> 10, j = n & 1023;
        const float* W = (g == 0) ? Wxr : ((g == 1) ? Wxc : Wxz);
        float4 v = *(const float4*)(W + (size_t)j * IN + kq * 4);
        float h0, l0, h1, l1, h2, l2, h3, l3;
        bfsplit(v.x, h0, l0); bfsplit(v.y, h1, l1);
        bfsplit(v.z, h2, l2); bfsplit(v.w, h3, l3);
        ((u32*)g_wxhi)[i4 * 2 + 0] = bfpack(h0, h1);
        ((u32*)g_wxhi)[i4 * 2 + 1] = bfpack(h2, h3);
        ((u32*)g_wxlo)[i4 * 2 + 0] = bfpack(l0, l1);
        ((u32*)g_wxlo)[i4 * 2 + 1] = bfpack(l2, l3);
    }
    if (i4 < G3) {
        int g = i4 >> 10, j = i4 & 1023;
        g_bxcat[i4] = ((g == 0) ? bxr : ((g == 1) ? bxc : bxz))[j];
    }
}

// ---------------------------------------------------------------------------
// X projection via bf16-split tensor cores (proven in R12, unchanged).
__global__ void __launch_bounds__(NTHR, 1)
gemm_x_mma_kernel() {
    extern __shared__ unsigned char smem[];
    const u32 sb = (u32)__cvta_generic_to_shared(smem);

    const int tid = threadIdx.x;
    const int w = tid >> 5, l = tid & 31;
    const int n0 = blockIdx.x * 128;
    const int m0 = blockIdx.y * 128;
    const int wm = w >> 1, wn = w & 1;

    const int lrow = (l & 7) | (((l >> 3) & 1) << 3);
    const int cb   = (l >> 4) * 16;
    const int lswz = (lrow & 7) * 16;
    const int brow = (l & 7) | ((l >> 4) << 3);
    const int bsg  = ((l >> 3) & 1) * 16;
    const int bswz = (l & 7) * 16;

    const int colp = (l & 3) * 2;
    float2 bias[8];
#pragma unroll
    for (int nt = 0; nt < 8; nt++)
        bias[nt] = *(const float2*)(g_bxcat + n0 + wn * 64 + nt * 8 + colp);

    float acc[2][8][4];
#pragma unroll
    for (int i = 0; i < 2; i++)
#pragma unroll
        for (int j = 0; j < 8; j++)
#pragma unroll
            for (int d = 0; d < 4; d++) acc[i][j][d] = 0.0f;

    auto stage = [&](int kc, int buf) {
#pragma unroll
        for (int p = 0; p < 4; p++) {
            int i = p * NTHR + tid;
            int row = i >> 3, seg = i & 7;
            u32 sw = (u32)((seg ^ (row & 7)) * 16);
            const size_t asrc = (size_t)(m0 + row) * IN + kc * 64 + seg * 8;
            cpa16(sb + buf * XA_BUF + row * 128 + sw, g_xhi + asrc);
            cpa16(sb + buf * XA_BUF + XA_VAR + row * 128 + sw, g_xlo + asrc);
            const size_t bsrc = (size_t)(n0 + row) * IN + kc * 64 + seg * 8;
            cpa16(sb + XB_OFF + buf * XA_BUF + row * 128 + sw, g_wxhi + bsrc);
            cpa16(sb + XB_OFF + buf * XA_BUF + XA_VAR + row * 128 + sw, g_wxlo + bsrc);
        }
    };

    stage(0, 0);
    asm volatile("cp.async.commit_group;");

    for (int kc = 0; kc < 8; kc++) {
        if (kc < 7) {
            stage(kc + 1, (kc + 1) & 1);
            asm volatile("cp.async.commit_group;");
            asm volatile("cp.async.wait_group 1;");
        } else {
            asm volatile("cp.async.wait_group 0;");
        }
        __syncthreads();

        const u32 Ap = sb + (kc & 1) * XA_BUF;
        const u32 Bp = sb + XB_OFF + (kc & 1) * XA_BUF;
#pragma unroll
        for (int ktl = 0; ktl < 4; ktl++) {
            u32 Ahi[2][4], Alo[2][4];
#pragma unroll
            for (int mtl = 0; mtl < 2; mtl++) {
                u32 a = Ap + (wm * 32 + mtl * 16 + lrow) * 128 +
                        (u32)((ktl * 32 + cb) ^ lswz);
                ldm_x4(Ahi[mtl], a);
                ldm_x4(Alo[mtl], a + XA_VAR);
            }
#pragma unroll
            for (int pair = 0; pair < 4; pair++) {
                u32 Bhi[4], Blo[4];
                u32 ba = Bp + (wn * 64 + pair * 16 + brow) * 128 +
                         (u32)((ktl * 32 + bsg) ^ bswz);
                ldm_x4(Bhi, ba);
                ldm_x4(Blo, ba + XA_VAR);
#pragma unroll
                for (int half = 0; half < 2; half++) {
                    u32 bh0 = Bhi[half * 2], bh1 = Bhi[half * 2 + 1];
                    u32 bl0 = Blo[half * 2], bl1 = Blo[half * 2 + 1];
                    const int nt = pair * 2 + half;
#pragma unroll
                    for (int mtl = 0; mtl < 2; mtl++) {
                        mma_bf16(acc[mtl][nt], Ahi[mtl], bh0, bh1);
                        mma_bf16(acc[mtl][nt], Ahi[mtl], bl0, bl1);
                        mma_bf16(acc[mtl][nt], Alo[mtl], bh0, bh1);
                    }
                }
            }
        }
        __syncthreads();
    }

#pragma unroll
    for (int mtl = 0; mtl < 2; mtl++) {
        const int r0 = m0 + wm * 32 + mtl * 16 + (l >> 2);
        const int b0 = r0 >> 9, t0 = r0 & (Tlen - 1);
        const int r1 = r0 + 8;
        const int b1 = r1 >> 9, t1 = r1 & (Tlen - 1);
        const size_t base0 = ((size_t)t0 * Bsz + b0) * G3 + n0 + wn * 64 + colp;
        const size_t base1 = ((size_t)t1 * Bsz + b1) * G3 + n0 + wn * 64 + colp;
#pragma unroll
        for (int nt = 0; nt < 8; nt++) {
            float2 o0, o1;
            o0.x = acc[mtl][nt][0] + bias[nt].x;
            o0.y = acc[mtl][nt][1] + bias[nt].y;
            o1.x = acc[mtl][nt][2] + bias[nt].x;
            o1.y = acc[mtl][nt][3] + bias[nt].y;
            *(float2*)(g_xpre + base0 + nt * 8) = o0;
            *(float2*)(g_xpre + base1 + nt * 8) = o1;
        }
    }
}

// ---------------------------------------------------------------------------
// Persistent GRU recurrence, re-tiled: grid (64 n-slices, 2 m-slices).
// CTA computes 128 rows x 48 cols (16/gate); reads only its 128 h-rows
// (512 KB/step vs 1 MB) -> halves L2 traffic. Warp-private h staging:
// each warp cp.asyncs its own 16-row A-tile (BK=32, 2 bufs), no CTA barriers
// in the k-loop. Weights (192 KB) fragment-packed in SMEM once.
__global__ void __launch_bounds__(NTHR, 1)
gru_persistent_kernel(const float* __restrict__ Whr, const float* __restrict__ bhr,
                      const float* __restrict__ Whc, const float* __restrict__ bhc,
                      const float* __restrict__ Whz, const float* __restrict__ bhz) {
    extern __shared__ unsigned char smem[];
    uint4* Wp = (uint4*)smem;
    const u32 sb = (u32)__cvta_generic_to_shared(smem);

    const int tid = threadIdx.x;
    const int w   = tid >> 5;
    const int l   = tid & 31;
    const int nsl = blockIdx.x;            // 0..63
    const int m0  = blockIdx.y * 128;      // 0 or 128
    const int nb0 = nsl * 16;              // per-gate column base

    // ---- Pack weight B-fragments once: Wp[g][kt][sub][lane] = {hi0,hi1,lo0,lo1}
    {
        const float* __restrict__ Wg[3] = {Whr, Whc, Whz};
        for (int e = tid; e < 3 * 64 * 2 * 32; e += NTHR) {
            int g = e >> 12, rem = e & 4095;
            int kt = rem >> 6;
            int sub = (rem >> 5) & 1;
            int lane = rem & 31;
            int n  = nb0 + sub * 8 + (lane >> 2);
            int k0 = kt * 16 + (lane & 3) * 2;
            const float* wr = Wg[g] + (size_t)n * HID + k0;
            float2 wa = *(const float2*)wr;        // k0, k0+1
            float2 wb = *(const float2*)(wr + 8);  // k0+8, k0+9
            float h0, l0, h1, l1, h8, l8, h9, l9;
            bfsplit(wa.x, h0, l0); bfsplit(wa.y, h1, l1);
            bfsplit(wb.x, h8, l8); bfsplit(wb.y, h9, l9);
            Wp[e] = make_uint4(bfpack(h0, h1), bfpack(h8, h9),
                               bfpack(l0, l1), bfpack(l8, l9));
        }
    }

    // ---- per-lane constants ----
    float2 bR[2], bC[2], bZ[2];
#pragma unroll
    for (int sub = 0; sub < 2; sub++) {
        int col = nb0 + sub * 8 + (l & 3) * 2;
        bR[sub] = *(const float2*)(bhr + col);
        bC[sub] = *(const float2*)(bhc + col);
        bZ[sub] = *(const float2*)(bhz + col);
    }

    // ldmatrix A lane addressing (16x16 b16 tile, 64-B rows, seg swizzle)
    const int lrow = (l & 7) | (((l >> 3) & 1) << 3);  // row within 16
    const int cbh  = l >> 4;                           // 16-B half 0/1
    const u32 hsbase = sb + HS_OFF + w * 4096;         // warp-private region

    // epilogue rows: R[q] = m0 + w*16 + (l>>2) + 8q
    const int R0 = m0 + w * 16 + (l >> 2);

    __syncthreads();

    for (int t = 0; t < Tlen; t++) {
        const int hb = t & 1, nb = hb ^ 1;

        // ---- prefetch epilogue operands (longest latency) ----
        float2 pxr[2][2], pxc[2][2], pxz[2][2], pho[2][2];
#pragma unroll
        for (int q = 0; q < 2; q++) {
            const int row = R0 + 8 * q;
            const size_t base = ((size_t)t * Bsz + row) * G3;
#pragma unroll
            for (int sub = 0; sub < 2; sub++) {
                const int col = nb0 + sub * 8 + (l & 3) * 2;
                pxr[q][sub] = *(const float2*)(g_xpre + base + col);
                pxc[q][sub] = *(const float2*)(g_xpre + base + HID + col);
                pxz[q][sub] = *(const float2*)(g_xpre + base + 2 * HID + col);
                pho[q][sub] = *(const float2*)(g_h[hb] + (size_t)row * HID + col);
            }
        }

        // warp-private staging: 16 rows x 32 k x 2 var per chunk (2 KB)
        const unsigned short* __restrict__ srcs[2] = {g_hhi[hb], g_hlo[hb]};
        auto stage = [&](int kc, int buf) {
#pragma unroll
            for (int j = 0; j < 4; j++) {
                int idx = j * 32 + l;                // 0..127
                int var = idx >> 6, rem = idx & 63;
                int row = rem >> 2, seg = rem & 3;
                const void* src = srcs[var] +
                    (size_t)(m0 + w * 16 + row) * HID + kc * 32 + seg * 8;
                u32 dst = hsbase + buf * 2048 + var * 1024 + row * 64 +
                          ((seg ^ ((row >> 1) & 3)) * 16);
                cpa16(dst, src);
            }
        };

        float acc[3][2][4];
#pragma unroll
        for (int g = 0; g < 3; g++)
#pragma unroll
            for (int s = 0; s < 2; s++)
#pragma unroll
                for (int d = 0; d < 4; d++) acc[g][s][d] = 0.0f;

        stage(0, 0);
        asm volatile("cp.async.commit_group;");
        stage(1, 1);
        asm volatile("cp.async.commit_group;");

        for (int kc = 0; kc < 32; kc++) {
            if (kc < 31) {
                asm volatile("cp.async.wait_group 1;");
            } else {
                asm volatile("cp.async.wait_group 0;");
            }
            __syncwarp();

            const u32 bufb = hsbase + (kc & 1) * 2048;
#pragma unroll
            for (int ktl = 0; ktl < 2; ktl++) {
                const int kt = kc * 2 + ktl;
                const int ps = ((ktl * 2 + cbh) ^ ((lrow >> 1) & 3)) * 16;
                u32 Ahi[4], Alo[4];
                ldm_x4(Ahi, bufb + lrow * 64 + ps);
                ldm_x4(Alo, bufb + 1024 + lrow * 64 + ps);
#pragma unroll
                for (int g = 0; g < 3; g++) {
#pragma unroll
                    for (int sub = 0; sub < 2; sub++) {
                        uint4 B = Wp[g * 4096 + kt * 64 + sub * 32 + l];
                        mma_bf16(acc[g][sub], Ahi, B.x, B.y);   // hh
                        mma_bf16(acc[g][sub], Ahi, B.z, B.w);   // hi*lo(W)
                        mma_bf16(acc[g][sub], Alo, B.x, B.y);   // lo(h)*hi
                    }
                }
            }

            if (kc < 30) {
                stage(kc + 2, kc & 1);
                asm volatile("cp.async.commit_group;");
            }
        }

        // ---- fused GRU elementwise update: 2 rows x 2 subs x 2 cols ----
#pragma unroll
        for (int q = 0; q < 2; q++) {
            const int row = R0 + 8 * q;
            const int d0 = q * 2;
#pragma unroll
            for (int sub = 0; sub < 2; sub++) {
                const int col = nb0 + sub * 8 + (l & 3) * 2;
                float aR0 = acc[0][sub][d0], aR1 = acc[0][sub][d0 + 1];
                float aC0 = acc[1][sub][d0], aC1 = acc[1][sub][d0 + 1];
                float aZ0 = acc[2][sub][d0], aZ1 = acc[2][sub][d0 + 1];

                float r0 = sigf(pxr[q][sub].x + aR0 + bR[sub].x);
                float r1 = sigf(pxr[q][sub].y + aR1 + bR[sub].y);
                float c0 = tanhf(pxc[q][sub].x + r0 * (aC0 + bC[sub].x));
                float c1 = tanhf(pxc[q][sub].y + r1 * (aC1 + bC[sub].y));
                float z0 = sigf(pxz[q][sub].x + aZ0 + bZ[sub].x);
                float z1 = sigf(pxz[q][sub].y + aZ1 + bZ[sub].y);
                float hn0 = (1.0f - z0) * pho[q][sub].x + z0 * c0;
                float hn1 = (1.0f - z1) * pho[q][sub].y + z1 * c1;

                const size_t off = (size_t)row * HID + col;
                float2 hv; hv.x = hn0; hv.y = hn1;
                *(float2*)(g_h[nb] + off) = hv;

                float h0f, l0f, h1f, l1f;
                bfsplit(hn0, h0f, l0f);
                bfsplit(hn1, h1f, l1f);
                ((u32*)g_hhi[nb])[off >> 1] = bfpack(h0f, h1f);
                ((u32*)g_hlo[nb])[off >> 1] = bfpack(l0f, l1f);
            }
        }

        // ---- grid barrier (monotonic counter; zeroed in-stream each launch) ----
        __syncthreads();
        if (tid == 0) {
            __threadfence();
            atomicAdd(&g_bar, 1u);
            const unsigned target = (unsigned)(t + 1) * (unsigned)NCTA;
            volatile unsigned* vb = &g_bar;
            while (*vb < target) __nanosleep(64);
            __threadfence();
        }
        __syncthreads();
    }
}

// ---------------------------------------------------------------------------
__global__ void gemm_out_kernel(const float* __restrict__ Wo, const float* __restrict__ bo,
                                float* __restrict__ out) {
    const int BKo = 32;
    __shared__ float HsO[BKo][32];
    __shared__ float WsO[BKo][64];

    const float* __restrict__ h = g_h[0];
    const int n0 = blockIdx.x * 64;
    const int m0 = blockIdx.y * 32;
    const int tid = threadIdx.x;

    const int hr = tid >> 2;
    const int hq = (tid & 3) * 8;
    const int wr = tid >> 1;
    const int wq = (tid & 1) * 16;
    const int tm = tid >> 4;
    const int tn = tid & 15;

    float acc[4][4];
#pragma unroll
    for (int i = 0; i < 4; i++)
#pragma unroll
        for (int j = 0; j < 4; j++) acc[i][j] = 0.f;

    for (int k0 = 0; k0 < HID; k0 += BKo) {
        {
            const float* hp = h + (size_t)(m0 + hr) * HID + k0 + hq;
            float4 h0 = *(const float4*)hp;
            float4 h1 = *(const float4*)(hp + 4);
            HsO[hq + 0][hr] = h0.x; HsO[hq + 1][hr] = h0.y;
            HsO[hq + 2][hr] = h0.z; HsO[hq + 3][hr] = h0.w;
            HsO[hq + 4][hr] = h1.x; HsO[hq + 5][hr] = h1.y;
            HsO[hq + 6][hr] = h1.z; HsO[hq + 7][hr] = h1.w;
        }
        {
            const float* wp = Wo + (size_t)(n0 + wr) * HID + k0 + wq;
#pragma unroll
            for (int u = 0; u < 4; u++) {
                float4 wv = *(const float4*)(wp + u * 4);
                WsO[wq + u * 4 + 0][wr] = wv.x;
                WsO[wq + u * 4 + 1][wr] = wv.y;
                WsO[wq + u * 4 + 2][wr] = wv.z;
                WsO[wq + u * 4 + 3][wr] = wv.w;
            }
        }
        __syncthreads();

#pragma unroll
        for (int k = 0; k < BKo; k++) {
            float4 hv = *(const float4*)&HsO[k][tm * 4];
            float4 wv = *(const float4*)&WsO[k][tn * 4];
            float h4[4] = {hv.x, hv.y, hv.z, hv.w};
            float w4[4] = {wv.x, wv.y, wv.z, wv.w};
#pragma unroll
            for (int i = 0; i < 4; i++)
#pragma unroll
                for (int j = 0; j < 4; j++)
                    acc[i][j] = fmaf(h4[i], w4[j], acc[i][j]);
        }
        __syncthreads();
    }

#pragma unroll
    for (int i = 0; i < 4; i++) {
        const int b = m0 + tm * 4 + i;
#pragma unroll
        for (int j = 0; j < 4; j++) {
            const int o = n0 + tn * 4 + j;
            out[(size_t)b * OUTD + o] = acc[i][j] + bo[o];
        }
    }
}

// ---------------------------------------------------------------------------
extern "C" void kernel_launch(void* const* d_in, const int* in_sizes, int n_in,
                              void* d_out, int out_size) {
    const float* x   = (const float*)d_in[0];
    const float* Wxr = (const float*)d_in[1];
    const float* bxr = (const float*)d_in[2];
    const float* Whr = (const float*)d_in[3];
    const float* bhr = (const float*)d_in[4];
    const float* Wxc = (const float*)d_in[5];
    const float* bxc = (const float*)d_in[6];
    const float* Whc = (const float*)d_in[7];
    const float* bhc = (const float*)d_in[8];
    const float* Wxz = (const float*)d_in[9];
    const float* bxz = (const float*)d_in[10];
    const float* Whz = (const float*)d_in[11];
    const float* bhz = (const float*)d_in[12];
    const float* Wo  = (const float*)d_in[13];
    const float* bo  = (const float*)d_in[14];
    float* out = (float*)d_out;

    cudaFuncSetAttribute(gru_persistent_kernel,
                         cudaFuncAttributeMaxDynamicSharedMemorySize, SMEM_BYTES);
    cudaFuncSetAttribute(gemm_x_mma_kernel,
                         cudaFuncAttributeMaxDynamicSharedMemorySize, XSMEM);

    zero_h_kernel<<<(Bsz * HID + 255) / 256, 256>>>();
    split_x_kernel<<<(int)(((size_t)Bsz * Tlen * IN / 4 + 255) / 256), 256>>>(x);
    split_w_kernel<<<(G3 * IN / 4 + 255) / 256, 256>>>(Wxr, Wxc, Wxz, bxr, bxc, bxz);
    gemm_x_mma_kernel<<<dim3(G3 / 128, (Bsz * Tlen) / 128), NTHR, XSMEM>>>();
    gru_persistent_kernel<<<dim3(64, 2), NTHR, SMEM_BYTES>>>(Whr, bhr, Whc, bhc, Whz, bhz);
    gemm_out_kernel<<<dim3(OUTD / 64, Bsz / 32), 128>>>(Wo, bo, out);
}